// round 1
// baseline (speedup 1.0000x reference)
#include <cuda_runtime.h>
#include <math.h>

// Problem constants
#define CB 2
#define CS 2048
#define CHID 1024
#define CH 8
#define CKV 4
#define CD 128
#define CBS (CB * CS)                 // 4096 rows
#define CSCALE 0.08838834764831845f   // 128^-0.5

// Scratch (allocation-free rule: __device__ globals)
__device__ float g_q[CBS * CH * CD];      // [b*S+s][h*128+d]
__device__ float g_k[CBS * CKV * CD];     // [b*S+s][kv*128+d]
__device__ float g_v[CBS * CKV * CD];
__device__ float g_bias[CBS * CH];        // dyn[b,s,h]
__device__ float g_attn[CBS * CH * CD];   // attention output, [b*S+s][h*128+d]

// ---------------------------------------------------------------------------
// Generic 128x128 fp32 tile GEMM, BK=16, 256 threads, 8x8 per thread.
// A row-major [.., K] (pre-offset to tile row 0), B row-major [K, ..]
// (pre-offset to tile col 0), C pre-offset to tile origin.
// ---------------------------------------------------------------------------
__device__ __forceinline__ void gemm_tile_128(
    const float* __restrict__ A, int lda,
    const float* __restrict__ Bw, int ldb,
    float* __restrict__ C, int ldc, int K)
{
    __shared__ float As[16][132];
    __shared__ float Bs[16][132];
    const int tid = threadIdx.x;
    const int tx = tid & 15;
    const int ty = tid >> 4;

    float acc[8][8];
#pragma unroll
    for (int i = 0; i < 8; ++i)
#pragma unroll
        for (int j = 0; j < 8; ++j) acc[i][j] = 0.f;

    const int ar = tid >> 2;          // 0..63
    const int ac = (tid & 3) << 2;    // 0,4,8,12
    const int br = tid >> 4;          // 0..15
    const int bc = (tid & 15) << 3;   // 0..120

    for (int k0 = 0; k0 < K; k0 += 16) {
        float4 a0 = *(const float4*)(A + (size_t)ar * lda + k0 + ac);
        float4 a1 = *(const float4*)(A + (size_t)(ar + 64) * lda + k0 + ac);
        As[ac + 0][ar] = a0.x; As[ac + 1][ar] = a0.y;
        As[ac + 2][ar] = a0.z; As[ac + 3][ar] = a0.w;
        As[ac + 0][ar + 64] = a1.x; As[ac + 1][ar + 64] = a1.y;
        As[ac + 2][ar + 64] = a1.z; As[ac + 3][ar + 64] = a1.w;
        *(float4*)&Bs[br][bc]     = *(const float4*)(Bw + (size_t)(k0 + br) * ldb + bc);
        *(float4*)&Bs[br][bc + 4] = *(const float4*)(Bw + (size_t)(k0 + br) * ldb + bc + 4);
        __syncthreads();
#pragma unroll
        for (int kk = 0; kk < 16; ++kk) {
            float a[8], b[8];
            *(float4*)&a[0] = *(const float4*)&As[kk][ty << 3];
            *(float4*)&a[4] = *(const float4*)&As[kk][(ty << 3) + 4];
            *(float4*)&b[0] = *(const float4*)&Bs[kk][tx << 3];
            *(float4*)&b[4] = *(const float4*)&Bs[kk][(tx << 3) + 4];
#pragma unroll
            for (int i = 0; i < 8; ++i)
#pragma unroll
                for (int j = 0; j < 8; ++j)
                    acc[i][j] = fmaf(a[i], b[j], acc[i][j]);
        }
        __syncthreads();
    }
#pragma unroll
    for (int i = 0; i < 8; ++i) {
        float* cp = C + (size_t)((ty << 3) + i) * ldc + (tx << 3);
        *(float4*)cp       = make_float4(acc[i][0], acc[i][1], acc[i][2], acc[i][3]);
        *(float4*)(cp + 4) = make_float4(acc[i][4], acc[i][5], acc[i][6], acc[i][7]);
    }
}

// ---------------------------------------------------------------------------
// Kernel 1: fused QKV projection.  N tiles: [0,1024)->q, [1024,1536)->k, rest->v
// ---------------------------------------------------------------------------
__global__ void __launch_bounds__(256) k_qkv(
    const float* __restrict__ hidden,
    const float* __restrict__ Wq,
    const float* __restrict__ Wk,
    const float* __restrict__ Wv)
{
    const int n0 = blockIdx.x * 128;
    const int m0 = blockIdx.y * 128;
    const float* A = hidden + (size_t)m0 * CHID;
    const float* Bw; int ldb; float* C; int ldc;
    if (n0 < 1024)      { Bw = Wq + n0;          ldb = 1024; C = g_q + (size_t)m0 * 1024 + n0;         ldc = 1024; }
    else if (n0 < 1536) { Bw = Wk + (n0 - 1024); ldb = 512;  C = g_k + (size_t)m0 * 512 + (n0 - 1024); ldc = 512;  }
    else                { Bw = Wv + (n0 - 1536); ldb = 512;  C = g_v + (size_t)m0 * 512 + (n0 - 1536); ldc = 512;  }
    gemm_tile_128(A, CHID, Bw, ldb, C, ldc, CHID);
}

// ---------------------------------------------------------------------------
// Kernel 2: RoPE on q and k (12 = H + KV heads, 64 pairs each)
// ---------------------------------------------------------------------------
__global__ void k_rope(const float* __restrict__ cosb, const float* __restrict__ sinb)
{
    const int t = blockIdx.x * blockDim.x + threadIdx.x;
    const int total = CBS * 12 * 64;
    if (t >= total) return;
    const int d = t & 63;
    const int head = (t >> 6) % 12;
    const int row = t / (12 * 64);
    const int s = row & (CS - 1);
    const float c1  = cosb[s * CD + d];
    const float sn1 = sinb[s * CD + d];
    const float c2  = cosb[s * CD + d + 64];
    const float sn2 = sinb[s * CD + d + 64];
    float* p;
    if (head < CH) p = g_q + (size_t)row * (CH * CD) + head * CD;
    else           p = g_k + (size_t)row * (CKV * CD) + (head - CH) * CD;
    const float x1 = p[d], x2 = p[d + 64];
    p[d]      = x1 * c1 - x2 * sn1;
    p[d + 64] = x2 * c2 + x1 * sn2;
}

// ---------------------------------------------------------------------------
// Kernel 3: dt = v_flat @ Wdt ; dyn = exp(A * softplus(dt))  (one warp per row)
// ---------------------------------------------------------------------------
__global__ void __launch_bounds__(256) k_biask(
    const float* __restrict__ Wdt, const float* __restrict__ Aw)
{
    __shared__ float sW[512 * 8];
    for (int i = threadIdx.x; i < 512 * 8; i += 256) sW[i] = Wdt[i];
    __syncthreads();
    const int warp = threadIdx.x >> 5;
    const int lane = threadIdx.x & 31;
    const int row = blockIdx.x * 8 + warp;
    const float* vrow = g_v + (size_t)row * 512;
    float acc[8];
#pragma unroll
    for (int h = 0; h < 8; ++h) acc[h] = 0.f;
    for (int j = lane; j < 512; j += 32) {
        const float vv = vrow[j];
#pragma unroll
        for (int h = 0; h < 8; ++h) acc[h] = fmaf(vv, sW[j * 8 + h], acc[h]);
    }
#pragma unroll
    for (int off = 16; off > 0; off >>= 1)
#pragma unroll
        for (int h = 0; h < 8; ++h)
            acc[h] += __shfl_xor_sync(0xffffffffu, acc[h], off);
    if (lane < 8) {
        const float dt = acc[lane];
        const float sp = (dt > 20.f) ? dt : log1pf(expf(dt));
        g_bias[(size_t)row * 8 + lane] = expf(Aw[lane] * sp);
    }
}

// ---------------------------------------------------------------------------
// Kernel 4: causal flash attention, fp32, key-wise bias.
// Block: 128 q rows x (loop of 64-key tiles), 256 threads (16x16).
// Thread (tx,ty): GEMM1 tile 8q x 4k, GEMM2 tile 8q x 8d. Row stats replicated
// across the 16 tx lanes (contiguous lanes -> shfl_xor width-16 reductions).
// ---------------------------------------------------------------------------
#define QT_S 132
#define KT_S 68
#define VS_S 128
#define PS_S 132
#define ATTN_SMEM_FLOATS (128 * QT_S + 128 * KT_S + 64 * VS_S + 64 * PS_S + 64)
#define ATTN_SMEM_BYTES (ATTN_SMEM_FLOATS * 4)

__global__ void __launch_bounds__(256, 1) k_attn()
{
    extern __shared__ float sm[];
    float* Qt = sm;                       // [d][q]  transposed
    float* Kt = Qt + 128 * QT_S;          // [d][key] transposed
    float* Vs = Kt + 128 * KT_S;          // [key][d]
    float* Ps = Vs + 64 * VS_S;           // [key][q] transposed
    float* bias_s = Ps + 64 * PS_S;       // [key]

    const int tid = threadIdx.x;
    const int tx = tid & 15;
    const int ty = tid >> 4;
    const int bh = blockIdx.x;
    const int b = bh >> 3;
    const int h = bh & 7;
    const int kvh = h >> 1;                       // GQA: 2 q heads per kv head
    const int qt = (int)gridDim.y - 1 - (int)blockIdx.y;  // heavy tiles first
    const int q0 = qt * 128;

    // Load Q tile transposed
    for (int ch = tid; ch < 128 * 32; ch += 256) {
        const int qi = ch >> 5;
        const int dc = (ch & 31) << 2;
        float4 v = *(const float4*)(g_q + (size_t)(b * CS + q0 + qi) * (CH * CD) + h * CD + dc);
        Qt[(dc + 0) * QT_S + qi] = v.x;
        Qt[(dc + 1) * QT_S + qi] = v.y;
        Qt[(dc + 2) * QT_S + qi] = v.z;
        Qt[(dc + 3) * QT_S + qi] = v.w;
    }

    float O[8][8], m[8], l[8];
#pragma unroll
    for (int i = 0; i < 8; ++i) {
        m[i] = -1e30f; l[i] = 0.f;
#pragma unroll
        for (int j = 0; j < 8; ++j) O[i][j] = 0.f;
    }

    const int nkt = 2 * qt + 2;      // causal: only tiles with keys <= q0+127
    for (int kt = 0; kt < nkt; ++kt) {
        const int kbase = kt * 64;
        for (int ch = tid; ch < 64 * 32; ch += 256) {
            const int c = ch >> 5;
            const int dc = (ch & 31) << 2;
            const size_t grow = (size_t)(b * CS + kbase + c) * (CKV * CD) + kvh * CD + dc;
            float4 kv = *(const float4*)(g_k + grow);
            Kt[(dc + 0) * KT_S + c] = kv.x;
            Kt[(dc + 1) * KT_S + c] = kv.y;
            Kt[(dc + 2) * KT_S + c] = kv.z;
            Kt[(dc + 3) * KT_S + c] = kv.w;
            *(float4*)&Vs[c * VS_S + dc] = *(const float4*)(g_v + grow);
        }
        if (tid < 64) bias_s[tid] = g_bias[(size_t)(b * CS + kbase + tid) * CH + h];
        __syncthreads();

        // GEMM1: scores 8x4
        float sacc[8][4];
#pragma unroll
        for (int i = 0; i < 8; ++i)
#pragma unroll
            for (int j = 0; j < 4; ++j) sacc[i][j] = 0.f;
#pragma unroll 8
        for (int d = 0; d < 128; ++d) {
            float a[8], kf[4];
            *(float4*)&a[0] = *(const float4*)&Qt[d * QT_S + (ty << 3)];
            *(float4*)&a[4] = *(const float4*)&Qt[d * QT_S + (ty << 3) + 4];
            *(float4*)&kf[0] = *(const float4*)&Kt[d * KT_S + (tx << 2)];
#pragma unroll
            for (int i = 0; i < 8; ++i)
#pragma unroll
                for (int j = 0; j < 4; ++j)
                    sacc[i][j] = fmaf(a[i], kf[j], sacc[i][j]);
        }

        float biasr[4];
#pragma unroll
        for (int j = 0; j < 4; ++j) biasr[j] = bias_s[(tx << 2) + j];

        float alpha[8];
#pragma unroll
        for (int i = 0; i < 8; ++i) {
            const int qg = q0 + (ty << 3) + i;
#pragma unroll
            for (int j = 0; j < 4; ++j) {
                const int kg = kbase + (tx << 2) + j;
                sacc[i][j] = (kg <= qg) ? fmaf(sacc[i][j], CSCALE, biasr[j]) : -1e30f;
            }
            float mloc = fmaxf(fmaxf(sacc[i][0], sacc[i][1]), fmaxf(sacc[i][2], sacc[i][3]));
#pragma unroll
            for (int off = 8; off > 0; off >>= 1)
                mloc = fmaxf(mloc, __shfl_xor_sync(0xffffffffu, mloc, off));
            const float mnew = fmaxf(m[i], mloc);
            alpha[i] = __expf(m[i] - mnew);
            float lt = 0.f;
#pragma unroll
            for (int j = 0; j < 4; ++j) {
                const float p = __expf(sacc[i][j] - mnew);
                sacc[i][j] = p;
                lt += p;
            }
#pragma unroll
            for (int off = 8; off > 0; off >>= 1)
                lt += __shfl_xor_sync(0xffffffffu, lt, off);
            l[i] = l[i] * alpha[i] + lt;
            m[i] = mnew;
        }

        // stage P transposed for GEMM2
#pragma unroll
        for (int j = 0; j < 4; ++j)
#pragma unroll
            for (int i = 0; i < 8; ++i)
                Ps[((tx << 2) + j) * PS_S + (ty << 3) + i] = sacc[i][j];
        __syncthreads();

#pragma unroll
        for (int i = 0; i < 8; ++i)
#pragma unroll
            for (int j = 0; j < 8; ++j) O[i][j] *= alpha[i];
#pragma unroll 8
        for (int kk = 0; kk < 64; ++kk) {
            float p8[8], v8[8];
            *(float4*)&p8[0] = *(const float4*)&Ps[kk * PS_S + (ty << 3)];
            *(float4*)&p8[4] = *(const float4*)&Ps[kk * PS_S + (ty << 3) + 4];
            *(float4*)&v8[0] = *(const float4*)&Vs[kk * VS_S + (tx << 3)];
            *(float4*)&v8[4] = *(const float4*)&Vs[kk * VS_S + (tx << 3) + 4];
#pragma unroll
            for (int i = 0; i < 8; ++i)
#pragma unroll
                for (int j = 0; j < 8; ++j)
                    O[i][j] = fmaf(p8[i], v8[j], O[i][j]);
        }
        __syncthreads();
    }

#pragma unroll
    for (int i = 0; i < 8; ++i) {
        const float inv = 1.f / l[i];
        float* op = g_attn + (size_t)(b * CS + q0 + (ty << 3) + i) * (CH * CD) + h * CD + (tx << 3);
        *(float4*)op       = make_float4(O[i][0] * inv, O[i][1] * inv, O[i][2] * inv, O[i][3] * inv);
        *(float4*)(op + 4) = make_float4(O[i][4] * inv, O[i][5] * inv, O[i][6] * inv, O[i][7] * inv);
    }
}

// ---------------------------------------------------------------------------
// Kernel 5: output projection  g_attn[4096,1024] @ Wo[1024,1024] -> out
// ---------------------------------------------------------------------------
__global__ void __launch_bounds__(256) k_out(const float* __restrict__ Wo, float* __restrict__ out)
{
    const int n0 = blockIdx.x * 128;
    const int m0 = blockIdx.y * 128;
    gemm_tile_128(g_attn + (size_t)m0 * 1024, 1024, Wo + n0, 1024,
                  out + (size_t)m0 * 1024 + n0, 1024, 1024);
}

// ---------------------------------------------------------------------------
extern "C" void kernel_launch(void* const* d_in, const int* in_sizes, int n_in,
                              void* d_out, int out_size)
{
    const float* hidden = (const float*)d_in[0];
    const float* Wq     = (const float*)d_in[1];
    const float* Wk     = (const float*)d_in[2];
    const float* Wv     = (const float*)d_in[3];
    const float* Wdt    = (const float*)d_in[4];
    const float* Aw     = (const float*)d_in[5];
    const float* Wo     = (const float*)d_in[6];
    const float* cosb   = (const float*)d_in[7];
    const float* sinb   = (const float*)d_in[8];
    // d_in[9] = causal_mask: implied by position, not read.
    float* out = (float*)d_out;

    // Idempotent, non-stream op: safe to repeat on every call (incl. capture).
    cudaFuncSetAttribute(k_attn, cudaFuncAttributeMaxDynamicSharedMemorySize,
                         ATTN_SMEM_BYTES);

    k_qkv<<<dim3(16, 32), 256>>>(hidden, Wq, Wk, Wv);
    k_rope<<<(CBS * 12 * 64 + 255) / 256, 256>>>(cosb, sinb);
    k_biask<<<CBS / 8, 256>>>(Wdt, Aw);
    k_attn<<<dim3(16, 16), 256, ATTN_SMEM_BYTES>>>();
    k_out<<<dim3(8, 32), 256>>>(Wo, out);
}

// round 4
// speedup vs baseline: 1.1160x; 1.1160x over previous
#include <cuda_runtime.h>
#include <math.h>

// Problem constants
#define CB 2
#define CS 2048
#define CHID 1024
#define CH 8
#define CKV 4
#define CD 128
#define CBS (CB * CS)                 // 4096 rows
#define CSCALE 0.08838834764831845f   // 128^-0.5

// Scratch (allocation-free rule: __device__ globals)
__device__ float g_q[CBS * CH * CD];      // [b*S+s][h*128+d]
__device__ float g_k[CBS * CKV * CD];     // [b*S+s][kv*128+d]
__device__ float g_v[CBS * CKV * CD];
__device__ float g_bias[CBS * CH];        // dyn[b,s,h]
__device__ float g_attn[CBS * CH * CD];   // attention output

// ===========================================================================
// 3xTF32 tensor-core GEMM: C[128,128] tile = A[128,K] @ B[K,128], K=1024.
// 8 warps (2M x 4N), warp tile 64x32, mma.sync m16n8k8 tf32.
// Each operand split x = hi + lo (tf32 pair); acc += hi*hi + hi*lo + lo*hi
// -> fp32-equivalent accuracy on the tensor pipe.
// cp.async double-buffered smem. A pad 36, B pad 132 (conflict-free frags).
// ===========================================================================
#define GEMM_SMEM_FLOATS (2 * 128 * 36 + 2 * 32 * 132)
#define GEMM_SMEM_BYTES (GEMM_SMEM_FLOATS * 4)

__device__ __forceinline__ void cp16(unsigned dst, const void* src) {
    asm volatile("cp.async.cg.shared.global [%0], [%1], 16;\n" :: "r"(dst), "l"(src));
}

__device__ __forceinline__ unsigned f2tf32(float x) {
    unsigned r;
    asm("cvt.rna.tf32.f32 %0, %1;\n" : "=r"(r) : "f"(x));
    return r;
}

// returns hi bits; writes lo bits
__device__ __forceinline__ unsigned tf32_split(float x, unsigned& lo) {
    const unsigned hi = f2tf32(x);
    lo = f2tf32(x - __uint_as_float(hi));
    return hi;
}

__device__ __forceinline__ void mma_tf32(float* d, const unsigned* a, const unsigned* b) {
    asm volatile(
        "mma.sync.aligned.m16n8k8.row.col.f32.tf32.tf32.f32 "
        "{%0,%1,%2,%3}, {%4,%5,%6,%7}, {%8,%9}, {%0,%1,%2,%3};\n"
        : "+f"(d[0]), "+f"(d[1]), "+f"(d[2]), "+f"(d[3])
        : "r"(a[0]), "r"(a[1]), "r"(a[2]), "r"(a[3]), "r"(b[0]), "r"(b[1]));
}

__device__ __forceinline__ void gemm128_3xtf32(
    const float* __restrict__ A, int lda,
    const float* __restrict__ B, int ldb,
    float* __restrict__ C, int ldc)
{
    extern __shared__ float sm[];
    float* As = sm;                 // [2][128*36]
    float* Bs = sm + 2 * 4608;      // [2][32*132]
    const unsigned asBase = (unsigned)__cvta_generic_to_shared(As);
    const unsigned bsBase = (unsigned)__cvta_generic_to_shared(Bs);

    const int tid = threadIdx.x;
    const int w = tid >> 5, lane = tid & 31;
    const int g = lane >> 2, t = lane & 3;
    const int rb = (w >> 2) * 64;   // warp row base (2 warps in M)
    const int cb = (w & 3) * 32;    // warp col base (4 warps in N)

    float acc[4][4][4];
#pragma unroll
    for (int mt = 0; mt < 4; ++mt)
#pragma unroll
        for (int nt = 0; nt < 4; ++nt)
#pragma unroll
            for (int r = 0; r < 4; ++r) acc[mt][nt][r] = 0.f;

    auto issue = [&](int k0, int s) {
#pragma unroll
        for (int i = 0; i < 4; ++i) {
            const int idx = tid + i * 256;
            const int r = idx >> 3, c = (idx & 7) << 2;
            cp16(asBase + (unsigned)((s * 4608 + r * 36 + c) << 2),
                 A + (size_t)r * lda + k0 + c);
        }
#pragma unroll
        for (int i = 0; i < 4; ++i) {
            const int idx = tid + i * 256;
            const int r = idx >> 5, c = (idx & 31) << 2;
            cp16(bsBase + (unsigned)((s * 4224 + r * 132 + c) << 2),
                 B + (size_t)(k0 + r) * ldb + c);
        }
        asm volatile("cp.async.commit_group;\n");
    };

    issue(0, 0);
    int s = 0;
    for (int k0 = 0; k0 < 1024; k0 += 32) {
        asm volatile("cp.async.wait_group 0;\n");
        __syncthreads();
        if (k0 + 32 < 1024) issue(k0 + 32, s ^ 1);
        const float* AsS = As + s * 4608;
        const float* BsS = Bs + s * 4224;
#pragma unroll
        for (int ks = 0; ks < 4; ++ks) {
            const int kk = ks * 8;
            unsigned ah[4][4], al[4][4], bh[4][2], bl[4][2];
#pragma unroll
            for (int mt = 0; mt < 4; ++mt) {
                const float* p = AsS + (rb + mt * 16 + g) * 36 + kk + t;
                ah[mt][0] = tf32_split(p[0],          al[mt][0]);
                ah[mt][1] = tf32_split(p[8 * 36],     al[mt][1]);
                ah[mt][2] = tf32_split(p[4],          al[mt][2]);
                ah[mt][3] = tf32_split(p[8 * 36 + 4], al[mt][3]);
            }
#pragma unroll
            for (int nt = 0; nt < 4; ++nt) {
                const float* p = BsS + (kk + t) * 132 + cb + nt * 8 + g;
                bh[nt][0] = tf32_split(p[0],       bl[nt][0]);
                bh[nt][1] = tf32_split(p[4 * 132], bl[nt][1]);
            }
#pragma unroll
            for (int mt = 0; mt < 4; ++mt)
#pragma unroll
                for (int nt = 0; nt < 4; ++nt) {
                    mma_tf32(acc[mt][nt], al[mt], bh[nt]);   // lo*hi
                    mma_tf32(acc[mt][nt], ah[mt], bl[nt]);   // hi*lo
                    mma_tf32(acc[mt][nt], ah[mt], bh[nt]);   // hi*hi
                }
        }
        s ^= 1;
    }

#pragma unroll
    for (int mt = 0; mt < 4; ++mt)
#pragma unroll
        for (int nt = 0; nt < 4; ++nt) {
            const int r0 = rb + mt * 16 + g;
            const int c0 = cb + nt * 8 + 2 * t;
            *(float2*)(C + (size_t)r0 * ldc + c0) =
                make_float2(acc[mt][nt][0], acc[mt][nt][1]);
            *(float2*)(C + (size_t)(r0 + 8) * ldc + c0) =
                make_float2(acc[mt][nt][2], acc[mt][nt][3]);
        }
}

// Kernel 1: fused QKV projection (3xTF32 MMA)
__global__ void __launch_bounds__(256) k_qkv_tc(
    const float* __restrict__ hidden,
    const float* __restrict__ Wq,
    const float* __restrict__ Wk,
    const float* __restrict__ Wv)
{
    const int n0 = blockIdx.x * 128;
    const int m0 = blockIdx.y * 128;
    const float* A = hidden + (size_t)m0 * CHID;
    const float* Bw; int ldb; float* C; int ldc;
    if (n0 < 1024)      { Bw = Wq + n0;          ldb = 1024; C = g_q + (size_t)m0 * 1024 + n0;         ldc = 1024; }
    else if (n0 < 1536) { Bw = Wk + (n0 - 1024); ldb = 512;  C = g_k + (size_t)m0 * 512 + (n0 - 1024); ldc = 512;  }
    else                { Bw = Wv + (n0 - 1536); ldb = 512;  C = g_v + (size_t)m0 * 512 + (n0 - 1536); ldc = 512;  }
    gemm128_3xtf32(A, CHID, Bw, ldb, C, ldc);
}

// Kernel 5: output projection (3xTF32 MMA)
__global__ void __launch_bounds__(256) k_out_tc(
    const float* __restrict__ Wo, float* __restrict__ out)
{
    const int n0 = blockIdx.x * 128;
    const int m0 = blockIdx.y * 128;
    gemm128_3xtf32(g_attn + (size_t)m0 * 1024, 1024, Wo + n0, 1024,
                   out + (size_t)m0 * 1024 + n0, 1024);
}

// ---------------------------------------------------------------------------
// Kernel 2: RoPE on q and k (12 = H + KV heads, 64 pairs each)
// ---------------------------------------------------------------------------
__global__ void k_rope(const float* __restrict__ cosb, const float* __restrict__ sinb)
{
    const int t = blockIdx.x * blockDim.x + threadIdx.x;
    const int total = CBS * 12 * 64;
    if (t >= total) return;
    const int d = t & 63;
    const int head = (t >> 6) % 12;
    const int row = t / (12 * 64);
    const int s = row & (CS - 1);
    const float c1  = cosb[s * CD + d];
    const float sn1 = sinb[s * CD + d];
    const float c2  = cosb[s * CD + d + 64];
    const float sn2 = sinb[s * CD + d + 64];
    float* p;
    if (head < CH) p = g_q + (size_t)row * (CH * CD) + head * CD;
    else           p = g_k + (size_t)row * (CKV * CD) + (head - CH) * CD;
    const float x1 = p[d], x2 = p[d + 64];
    p[d]      = x1 * c1 - x2 * sn1;
    p[d + 64] = x2 * c2 + x1 * sn2;
}

// ---------------------------------------------------------------------------
// Kernel 3: dt = v_flat @ Wdt ; dyn = exp(A * softplus(dt))  (one warp per row)
// ---------------------------------------------------------------------------
__global__ void __launch_bounds__(256) k_biask(
    const float* __restrict__ Wdt, const float* __restrict__ Aw)
{
    __shared__ float sW[512 * 8];
    for (int i = threadIdx.x; i < 512 * 8; i += 256) sW[i] = Wdt[i];
    __syncthreads();
    const int warp = threadIdx.x >> 5;
    const int lane = threadIdx.x & 31;
    const int row = blockIdx.x * 8 + warp;
    const float* vrow = g_v + (size_t)row * 512;
    float acc[8];
#pragma unroll
    for (int h = 0; h < 8; ++h) acc[h] = 0.f;
    for (int j = lane; j < 512; j += 32) {
        const float vv = vrow[j];
#pragma unroll
        for (int h = 0; h < 8; ++h) acc[h] = fmaf(vv, sW[j * 8 + h], acc[h]);
    }
#pragma unroll
    for (int off = 16; off > 0; off >>= 1)
#pragma unroll
        for (int h = 0; h < 8; ++h)
            acc[h] += __shfl_xor_sync(0xffffffffu, acc[h], off);
    if (lane < 8) {
        const float dt = acc[lane];
        const float sp = (dt > 20.f) ? dt : log1pf(expf(dt));
        g_bias[(size_t)row * 8 + lane] = expf(Aw[lane] * sp);
    }
}

// ---------------------------------------------------------------------------
// Kernel 4: causal flash attention, fp32 (unchanged this round)
// ---------------------------------------------------------------------------
#define QT_S 132
#define KT_S 68
#define VS_S 128
#define PS_S 132
#define ATTN_SMEM_FLOATS (128 * QT_S + 128 * KT_S + 64 * VS_S + 64 * PS_S + 64)
#define ATTN_SMEM_BYTES (ATTN_SMEM_FLOATS * 4)

__global__ void __launch_bounds__(256, 1) k_attn()
{
    extern __shared__ float sm[];
    float* Qt = sm;                       // [d][q]  transposed
    float* Kt = Qt + 128 * QT_S;          // [d][key] transposed
    float* Vs = Kt + 128 * KT_S;          // [key][d]
    float* Ps = Vs + 64 * VS_S;           // [key][q] transposed
    float* bias_s = Ps + 64 * PS_S;       // [key]

    const int tid = threadIdx.x;
    const int tx = tid & 15;
    const int ty = tid >> 4;
    const int bh = blockIdx.x;
    const int b = bh >> 3;
    const int h = bh & 7;
    const int kvh = h >> 1;
    const int qt = (int)gridDim.y - 1 - (int)blockIdx.y;
    const int q0 = qt * 128;

    for (int ch = tid; ch < 128 * 32; ch += 256) {
        const int qi = ch >> 5;
        const int dc = (ch & 31) << 2;
        float4 v = *(const float4*)(g_q + (size_t)(b * CS + q0 + qi) * (CH * CD) + h * CD + dc);
        Qt[(dc + 0) * QT_S + qi] = v.x;
        Qt[(dc + 1) * QT_S + qi] = v.y;
        Qt[(dc + 2) * QT_S + qi] = v.z;
        Qt[(dc + 3) * QT_S + qi] = v.w;
    }

    float O[8][8], m[8], l[8];
#pragma unroll
    for (int i = 0; i < 8; ++i) {
        m[i] = -1e30f; l[i] = 0.f;
#pragma unroll
        for (int j = 0; j < 8; ++j) O[i][j] = 0.f;
    }

    const int nkt = 2 * qt + 2;
    for (int kt = 0; kt < nkt; ++kt) {
        const int kbase = kt * 64;
        for (int ch = tid; ch < 64 * 32; ch += 256) {
            const int c = ch >> 5;
            const int dc = (ch & 31) << 2;
            const size_t grow = (size_t)(b * CS + kbase + c) * (CKV * CD) + kvh * CD + dc;
            float4 kv = *(const float4*)(g_k + grow);
            Kt[(dc + 0) * KT_S + c] = kv.x;
            Kt[(dc + 1) * KT_S + c] = kv.y;
            Kt[(dc + 2) * KT_S + c] = kv.z;
            Kt[(dc + 3) * KT_S + c] = kv.w;
            *(float4*)&Vs[c * VS_S + dc] = *(const float4*)(g_v + grow);
        }
        if (tid < 64) bias_s[tid] = g_bias[(size_t)(b * CS + kbase + tid) * CH + h];
        __syncthreads();

        float sacc[8][4];
#pragma unroll
        for (int i = 0; i < 8; ++i)
#pragma unroll
            for (int j = 0; j < 4; ++j) sacc[i][j] = 0.f;
#pragma unroll 8
        for (int d = 0; d < 128; ++d) {
            float a[8], kf[4];
            *(float4*)&a[0] = *(const float4*)&Qt[d * QT_S + (ty << 3)];
            *(float4*)&a[4] = *(const float4*)&Qt[d * QT_S + (ty << 3) + 4];
            *(float4*)&kf[0] = *(const float4*)&Kt[d * KT_S + (tx << 2)];
#pragma unroll
            for (int i = 0; i < 8; ++i)
#pragma unroll
                for (int j = 0; j < 4; ++j)
                    sacc[i][j] = fmaf(a[i], kf[j], sacc[i][j]);
        }

        float biasr[4];
#pragma unroll
        for (int j = 0; j < 4; ++j) biasr[j] = bias_s[(tx << 2) + j];

        float alpha[8];
#pragma unroll
        for (int i = 0; i < 8; ++i) {
            const int qg = q0 + (ty << 3) + i;
#pragma unroll
            for (int j = 0; j < 4; ++j) {
                const int kg = kbase + (tx << 2) + j;
                sacc[i][j] = (kg <= qg) ? fmaf(sacc[i][j], CSCALE, biasr[j]) : -1e30f;
            }
            float mloc = fmaxf(fmaxf(sacc[i][0], sacc[i][1]), fmaxf(sacc[i][2], sacc[i][3]));
#pragma unroll
            for (int off = 8; off > 0; off >>= 1)
                mloc = fmaxf(mloc, __shfl_xor_sync(0xffffffffu, mloc, off));
            const float mnew = fmaxf(m[i], mloc);
            alpha[i] = __expf(m[i] - mnew);
            float lt = 0.f;
#pragma unroll
            for (int j = 0; j < 4; ++j) {
                const float p = __expf(sacc[i][j] - mnew);
                sacc[i][j] = p;
                lt += p;
            }
#pragma unroll
            for (int off = 8; off > 0; off >>= 1)
                lt += __shfl_xor_sync(0xffffffffu, lt, off);
            l[i] = l[i] * alpha[i] + lt;
            m[i] = mnew;
        }

#pragma unroll
        for (int j = 0; j < 4; ++j)
#pragma unroll
            for (int i = 0; i < 8; ++i)
                Ps[((tx << 2) + j) * PS_S + (ty << 3) + i] = sacc[i][j];
        __syncthreads();

#pragma unroll
        for (int i = 0; i < 8; ++i)
#pragma unroll
            for (int j = 0; j < 8; ++j) O[i][j] *= alpha[i];
#pragma unroll 8
        for (int kk = 0; kk < 64; ++kk) {
            float p8[8], v8[8];
            *(float4*)&p8[0] = *(const float4*)&Ps[kk * PS_S + (ty << 3)];
            *(float4*)&p8[4] = *(const float4*)&Ps[kk * PS_S + (ty << 3) + 4];
            *(float4*)&v8[0] = *(const float4*)&Vs[kk * VS_S + (tx << 3)];
            *(float4*)&v8[4] = *(const float4*)&Vs[kk * VS_S + (tx << 3) + 4];
#pragma unroll
            for (int i = 0; i < 8; ++i)
#pragma unroll
                for (int j = 0; j < 8; ++j)
                    O[i][j] = fmaf(p8[i], v8[j], O[i][j]);
        }
        __syncthreads();
    }

#pragma unroll
    for (int i = 0; i < 8; ++i) {
        const float inv = 1.f / l[i];
        float* op = g_attn + (size_t)(b * CS + q0 + (ty << 3) + i) * (CH * CD) + h * CD + (tx << 3);
        *(float4*)op       = make_float4(O[i][0] * inv, O[i][1] * inv, O[i][2] * inv, O[i][3] * inv);
        *(float4*)(op + 4) = make_float4(O[i][4] * inv, O[i][5] * inv, O[i][6] * inv, O[i][7] * inv);
    }
}

// ---------------------------------------------------------------------------
extern "C" void kernel_launch(void* const* d_in, const int* in_sizes, int n_in,
                              void* d_out, int out_size)
{
    const float* hidden = (const float*)d_in[0];
    const float* Wq     = (const float*)d_in[1];
    const float* Wk     = (const float*)d_in[2];
    const float* Wv     = (const float*)d_in[3];
    const float* Wdt    = (const float*)d_in[4];
    const float* Aw     = (const float*)d_in[5];
    const float* Wo     = (const float*)d_in[6];
    const float* cosb   = (const float*)d_in[7];
    const float* sinb   = (const float*)d_in[8];
    float* out = (float*)d_out;

    cudaFuncSetAttribute(k_qkv_tc, cudaFuncAttributeMaxDynamicSharedMemorySize, GEMM_SMEM_BYTES);
    cudaFuncSetAttribute(k_out_tc, cudaFuncAttributeMaxDynamicSharedMemorySize, GEMM_SMEM_BYTES);
    cudaFuncSetAttribute(k_attn, cudaFuncAttributeMaxDynamicSharedMemorySize, ATTN_SMEM_BYTES);

    k_qkv_tc<<<dim3(16, 32), 256, GEMM_SMEM_BYTES>>>(hidden, Wq, Wk, Wv);
    k_rope<<<(CBS * 12 * 64 + 255) / 256, 256>>>(cosb, sinb);
    k_biask<<<CBS / 8, 256>>>(Wdt, Aw);
    k_attn<<<dim3(16, 16), 256, ATTN_SMEM_BYTES>>>();
    k_out_tc<<<dim3(8, 32), 256, GEMM_SMEM_BYTES>>>(Wo, out);
}

// round 5
// speedup vs baseline: 1.1525x; 1.0327x over previous
#include <cuda_runtime.h>
#include <math.h>

// Problem constants
#define CB 2
#define CS 2048
#define CHID 1024
#define CH 8
#define CKV 4
#define CD 128
#define CBS (CB * CS)                 // 4096 rows
#define CSCALE 0.08838834764831845f   // 128^-0.5

// Scratch (allocation-free rule: __device__ globals)
__device__ float g_q[CBS * CH * CD];      // [b*S+s][h*128+d]
__device__ float g_k[CBS * CKV * CD];     // [b*S+s][kv*128+d]
__device__ float g_v[CBS * CKV * CD];
__device__ float g_biasT[CH * CB * CS];   // dyn transposed: [h][b][s]
__device__ float g_attn[CBS * CH * CD];   // attention output

__device__ __forceinline__ void cp16(unsigned dst, const void* src) {
    asm volatile("cp.async.cg.shared.global [%0], [%1], 16;\n" :: "r"(dst), "l"(src));
}

__device__ __forceinline__ unsigned f2tf32(float x) {
    unsigned r;
    asm("cvt.rna.tf32.f32 %0, %1;\n" : "=r"(r) : "f"(x));
    return r;
}

__device__ __forceinline__ unsigned tf32_split(float x, unsigned& lo) {
    const unsigned hi = f2tf32(x);
    lo = f2tf32(x - __uint_as_float(hi));
    return hi;
}

__device__ __forceinline__ void mma_tf32(float* d, const unsigned* a, const unsigned* b) {
    asm volatile(
        "mma.sync.aligned.m16n8k8.row.col.f32.tf32.tf32.f32 "
        "{%0,%1,%2,%3}, {%4,%5,%6,%7}, {%8,%9}, {%0,%1,%2,%3};\n"
        : "+f"(d[0]), "+f"(d[1]), "+f"(d[2]), "+f"(d[3])
        : "r"(a[0]), "r"(a[1]), "r"(a[2]), "r"(a[3]), "r"(b[0]), "r"(b[1]));
}

// ===========================================================================
// 3xTF32 projection GEMM (unchanged from round 4; passing, rel_err 1.6e-5)
// ===========================================================================
#define GEMM_SMEM_FLOATS (2 * 128 * 36 + 2 * 32 * 132)
#define GEMM_SMEM_BYTES (GEMM_SMEM_FLOATS * 4)

__device__ __forceinline__ void gemm128_3xtf32(
    const float* __restrict__ A, int lda,
    const float* __restrict__ B, int ldb,
    float* __restrict__ C, int ldc)
{
    extern __shared__ float sm[];
    float* As = sm;                 // [2][128*36]
    float* Bs = sm + 2 * 4608;      // [2][32*132]
    const unsigned asBase = (unsigned)__cvta_generic_to_shared(As);
    const unsigned bsBase = (unsigned)__cvta_generic_to_shared(Bs);

    const int tid = threadIdx.x;
    const int w = tid >> 5, lane = tid & 31;
    const int g = lane >> 2, t = lane & 3;
    const int rb = (w >> 2) * 64;
    const int cb = (w & 3) * 32;

    float acc[4][4][4];
#pragma unroll
    for (int mt = 0; mt < 4; ++mt)
#pragma unroll
        for (int nt = 0; nt < 4; ++nt)
#pragma unroll
            for (int r = 0; r < 4; ++r) acc[mt][nt][r] = 0.f;

    auto issue = [&](int k0, int s) {
#pragma unroll
        for (int i = 0; i < 4; ++i) {
            const int idx = tid + i * 256;
            const int r = idx >> 3, c = (idx & 7) << 2;
            cp16(asBase + (unsigned)((s * 4608 + r * 36 + c) << 2),
                 A + (size_t)r * lda + k0 + c);
        }
#pragma unroll
        for (int i = 0; i < 4; ++i) {
            const int idx = tid + i * 256;
            const int r = idx >> 5, c = (idx & 31) << 2;
            cp16(bsBase + (unsigned)((s * 4224 + r * 132 + c) << 2),
                 B + (size_t)(k0 + r) * ldb + c);
        }
        asm volatile("cp.async.commit_group;\n");
    };

    issue(0, 0);
    int s = 0;
    for (int k0 = 0; k0 < 1024; k0 += 32) {
        asm volatile("cp.async.wait_group 0;\n");
        __syncthreads();
        if (k0 + 32 < 1024) issue(k0 + 32, s ^ 1);
        const float* AsS = As + s * 4608;
        const float* BsS = Bs + s * 4224;
#pragma unroll
        for (int ks = 0; ks < 4; ++ks) {
            const int kk = ks * 8;
            unsigned ah[4][4], al[4][4], bh[4][2], bl[4][2];
#pragma unroll
            for (int mt = 0; mt < 4; ++mt) {
                const float* p = AsS + (rb + mt * 16 + g) * 36 + kk + t;
                ah[mt][0] = tf32_split(p[0],          al[mt][0]);
                ah[mt][1] = tf32_split(p[8 * 36],     al[mt][1]);
                ah[mt][2] = tf32_split(p[4],          al[mt][2]);
                ah[mt][3] = tf32_split(p[8 * 36 + 4], al[mt][3]);
            }
#pragma unroll
            for (int nt = 0; nt < 4; ++nt) {
                const float* p = BsS + (kk + t) * 132 + cb + nt * 8 + g;
                bh[nt][0] = tf32_split(p[0],       bl[nt][0]);
                bh[nt][1] = tf32_split(p[4 * 132], bl[nt][1]);
            }
#pragma unroll
            for (int mt = 0; mt < 4; ++mt)
#pragma unroll
                for (int nt = 0; nt < 4; ++nt) {
                    mma_tf32(acc[mt][nt], al[mt], bh[nt]);
                    mma_tf32(acc[mt][nt], ah[mt], bl[nt]);
                    mma_tf32(acc[mt][nt], ah[mt], bh[nt]);
                }
        }
        s ^= 1;
    }

#pragma unroll
    for (int mt = 0; mt < 4; ++mt)
#pragma unroll
        for (int nt = 0; nt < 4; ++nt) {
            const int r0 = rb + mt * 16 + g;
            const int c0 = cb + nt * 8 + 2 * t;
            *(float2*)(C + (size_t)r0 * ldc + c0) =
                make_float2(acc[mt][nt][0], acc[mt][nt][1]);
            *(float2*)(C + (size_t)(r0 + 8) * ldc + c0) =
                make_float2(acc[mt][nt][2], acc[mt][nt][3]);
        }
}

__global__ void __launch_bounds__(256) k_qkv_tc(
    const float* __restrict__ hidden,
    const float* __restrict__ Wq,
    const float* __restrict__ Wk,
    const float* __restrict__ Wv)
{
    const int n0 = blockIdx.x * 128;
    const int m0 = blockIdx.y * 128;
    const float* A = hidden + (size_t)m0 * CHID;
    const float* Bw; int ldb; float* C; int ldc;
    if (n0 < 1024)      { Bw = Wq + n0;          ldb = 1024; C = g_q + (size_t)m0 * 1024 + n0;         ldc = 1024; }
    else if (n0 < 1536) { Bw = Wk + (n0 - 1024); ldb = 512;  C = g_k + (size_t)m0 * 512 + (n0 - 1024); ldc = 512;  }
    else                { Bw = Wv + (n0 - 1536); ldb = 512;  C = g_v + (size_t)m0 * 512 + (n0 - 1536); ldc = 512;  }
    gemm128_3xtf32(A, CHID, Bw, ldb, C, ldc);
}

__global__ void __launch_bounds__(256) k_out_tc(
    const float* __restrict__ Wo, float* __restrict__ out)
{
    const int n0 = blockIdx.x * 128;
    const int m0 = blockIdx.y * 128;
    gemm128_3xtf32(g_attn + (size_t)m0 * 1024, 1024, Wo + n0, 1024,
                   out + (size_t)m0 * 1024 + n0, 1024);
}

// ---------------------------------------------------------------------------
// Kernel 2: RoPE on q and k
// ---------------------------------------------------------------------------
__global__ void k_rope(const float* __restrict__ cosb, const float* __restrict__ sinb)
{
    const int t = blockIdx.x * blockDim.x + threadIdx.x;
    const int total = CBS * 12 * 64;
    if (t >= total) return;
    const int d = t & 63;
    const int head = (t >> 6) % 12;
    const int row = t / (12 * 64);
    const int s = row & (CS - 1);
    const float c1  = cosb[s * CD + d];
    const float sn1 = sinb[s * CD + d];
    const float c2  = cosb[s * CD + d + 64];
    const float sn2 = sinb[s * CD + d + 64];
    float* p;
    if (head < CH) p = g_q + (size_t)row * (CH * CD) + head * CD;
    else           p = g_k + (size_t)row * (CKV * CD) + (head - CH) * CD;
    const float x1 = p[d], x2 = p[d + 64];
    p[d]      = x1 * c1 - x2 * sn1;
    p[d + 64] = x2 * c2 + x1 * sn2;
}

// ---------------------------------------------------------------------------
// Kernel 3: dt = v_flat @ Wdt ; dyn = exp(A * softplus(dt))
// Now writes the TRANSPOSED bias layout [h][b][s] (contiguous in s).
// ---------------------------------------------------------------------------
__global__ void __launch_bounds__(256) k_biask(
    const float* __restrict__ Wdt, const float* __restrict__ Aw)
{
    __shared__ float sW[512 * 8];
    for (int i = threadIdx.x; i < 512 * 8; i += 256) sW[i] = Wdt[i];
    __syncthreads();
    const int warp = threadIdx.x >> 5;
    const int lane = threadIdx.x & 31;
    const int row = blockIdx.x * 8 + warp;
    const float* vrow = g_v + (size_t)row * 512;
    float acc[8];
#pragma unroll
    for (int h = 0; h < 8; ++h) acc[h] = 0.f;
    for (int j = lane; j < 512; j += 32) {
        const float vv = vrow[j];
#pragma unroll
        for (int h = 0; h < 8; ++h) acc[h] = fmaf(vv, sW[j * 8 + h], acc[h]);
    }
#pragma unroll
    for (int off = 16; off > 0; off >>= 1)
#pragma unroll
        for (int h = 0; h < 8; ++h)
            acc[h] += __shfl_xor_sync(0xffffffffu, acc[h], off);
    if (lane < 8) {
        const float dt = acc[lane];
        const float sp = (dt > 20.f) ? dt : log1pf(expf(dt));
        const int b = row >> 11;          // row / CS
        const int s = row & (CS - 1);
        g_biasT[(size_t)(lane * CB + b) * CS + s] = expf(Aw[lane] * sp);
    }
}

// ===========================================================================
// Kernel 4: causal flash attention on tensor cores (raw tf32 mma).
// 128 q-tile x 64 k-tile, 8 warps, warp = m16 rows. Q frags in registers.
// K/V double-buffered via cp.async. P relayout through warp-private smem.
// ===========================================================================
#define KSTR 132            // Ks row stride (banks (4g+t): conflict-free)
#define VSTR 136            // Vs row stride (banks (8t+g): conflict-free)
#define PSTR 68             // Ps row stride
#define AT_KS 0                         // 2 stages x 64*132
#define AT_VS (2 * 64 * KSTR)           // 16896
#define AT_PS (AT_VS + 2 * 64 * VSTR)   // 16896 + 17408 = 34304
#define AT_BIAS (AT_PS + 128 * PSTR)    // 34304 + 8704 = 43008
#define ATTN_TC_FLOATS (AT_BIAS + 2 * 64)
#define ATTN_TC_BYTES (ATTN_TC_FLOATS * 4)

__global__ void __launch_bounds__(256, 1) k_attn_tc()
{
    extern __shared__ float sm[];
    float* Ks = sm + AT_KS;
    float* Vs = sm + AT_VS;
    float* Ps = sm + AT_PS;
    float* bias_s = sm + AT_BIAS;
    const unsigned smBase = (unsigned)__cvta_generic_to_shared(sm);

    const int tid = threadIdx.x;
    const int w = tid >> 5, lane = tid & 31;
    const int g = lane >> 2, t = lane & 3;
    const int bh = blockIdx.x;
    const int b = bh >> 3;
    const int h = bh & 7;
    const int kvh = h >> 1;
    const int qt = (int)gridDim.y - 1 - (int)blockIdx.y;  // heavy tiles first
    const int q0 = qt * 128;
    const int qw = w * 16;                // warp's local q-row base
    const int qg0 = q0 + qw + g;          // global q rows held by this thread
    const int qg1 = qg0 + 8;

    // ---- Q fragments: loaded once, kept in registers (raw fp32 bits == tf32-RZ)
    unsigned aq[16][4];
    {
        const float* qp = g_q + (size_t)(b * CS + qg0) * 1024 + h * 128;
#pragma unroll
        for (int kf = 0; kf < 16; ++kf) {
            aq[kf][0] = __float_as_uint(qp[kf * 8 + t]);
            aq[kf][1] = __float_as_uint(qp[8 * 1024 + kf * 8 + t]);
            aq[kf][2] = __float_as_uint(qp[kf * 8 + t + 4]);
            aq[kf][3] = __float_as_uint(qp[8 * 1024 + kf * 8 + t + 4]);
        }
    }

    float O[16][4];
#pragma unroll
    for (int nt = 0; nt < 16; ++nt)
#pragma unroll
        for (int r = 0; r < 4; ++r) O[nt][r] = 0.f;
    float m0 = -1e30f, m1 = -1e30f, l0 = 0.f, l1 = 0.f;

    const int nkt = 2 * qt + 2;

    auto issue = [&](int kt, int st) {
        const int kbase = kt * 64;
#pragma unroll
        for (int i = 0; i < 8; ++i) {
            const int idx = tid + i * 256;
            const int c = idx >> 5, dc = (idx & 31) << 2;
            const size_t grow = (size_t)(b * CS + kbase + c) * 512 + kvh * 128 + dc;
            cp16(smBase + (unsigned)((AT_KS + st * 64 * KSTR + c * KSTR + dc) << 2), g_k + grow);
            cp16(smBase + (unsigned)((AT_VS + st * 64 * VSTR + c * VSTR + dc) << 2), g_v + grow);
        }
        if (tid < 16)
            cp16(smBase + (unsigned)((AT_BIAS + st * 64 + tid * 4) << 2),
                 g_biasT + (size_t)(h * CB + b) * CS + kbase + tid * 4);
        asm volatile("cp.async.commit_group;\n");
    };

    issue(0, 0);
    int st = 0;
    for (int kt = 0; kt < nkt; ++kt) {
        const int kbase = kt * 64;
        asm volatile("cp.async.wait_group 0;\n");
        __syncthreads();
        if (kt + 1 < nkt) issue(kt + 1, st ^ 1);

        const float* KsS = Ks + st * 64 * KSTR;
        const float* VsS = Vs + st * 64 * VSTR;
        const float* biasS = bias_s + st * 64;

        // ---- QK^T: scores m16 x n64, k=128
        float sacc[8][4];
#pragma unroll
        for (int nt = 0; nt < 8; ++nt)
#pragma unroll
            for (int r = 0; r < 4; ++r) sacc[nt][r] = 0.f;
#pragma unroll
        for (int kf = 0; kf < 16; ++kf) {
#pragma unroll
            for (int nt = 0; nt < 8; ++nt) {
                unsigned bf[2];
                const float* kp = KsS + (nt * 8 + g) * KSTR + kf * 8 + t;
                bf[0] = __float_as_uint(kp[0]);
                bf[1] = __float_as_uint(kp[4]);
                mma_tf32(sacc[nt], aq[kf], bf);
            }
        }

        // ---- softmax (rows g and g+8; reduce over 4-lane quad)
        float mx0 = -1e30f, mx1 = -1e30f;
#pragma unroll
        for (int nt = 0; nt < 8; ++nt) {
            const int kg = kbase + nt * 8 + 2 * t;
            const float b0 = biasS[nt * 8 + 2 * t];
            const float b1 = biasS[nt * 8 + 2 * t + 1];
            sacc[nt][0] = (kg     <= qg0) ? fmaf(sacc[nt][0], CSCALE, b0) : -1e30f;
            sacc[nt][1] = (kg + 1 <= qg0) ? fmaf(sacc[nt][1], CSCALE, b1) : -1e30f;
            sacc[nt][2] = (kg     <= qg1) ? fmaf(sacc[nt][2], CSCALE, b0) : -1e30f;
            sacc[nt][3] = (kg + 1 <= qg1) ? fmaf(sacc[nt][3], CSCALE, b1) : -1e30f;
            mx0 = fmaxf(mx0, fmaxf(sacc[nt][0], sacc[nt][1]));
            mx1 = fmaxf(mx1, fmaxf(sacc[nt][2], sacc[nt][3]));
        }
        mx0 = fmaxf(mx0, __shfl_xor_sync(0xffffffffu, mx0, 1));
        mx0 = fmaxf(mx0, __shfl_xor_sync(0xffffffffu, mx0, 2));
        mx1 = fmaxf(mx1, __shfl_xor_sync(0xffffffffu, mx1, 1));
        mx1 = fmaxf(mx1, __shfl_xor_sync(0xffffffffu, mx1, 2));

        const float mn0 = fmaxf(m0, mx0);
        const float mn1 = fmaxf(m1, mx1);
        const float alpha0 = __expf(m0 - mn0);
        const float alpha1 = __expf(m1 - mn1);
        float sum0 = 0.f, sum1 = 0.f;
#pragma unroll
        for (int nt = 0; nt < 8; ++nt) {
            const float p0 = __expf(sacc[nt][0] - mn0);
            const float p1 = __expf(sacc[nt][1] - mn0);
            const float p2 = __expf(sacc[nt][2] - mn1);
            const float p3 = __expf(sacc[nt][3] - mn1);
            sum0 += p0 + p1;
            sum1 += p2 + p3;
            *(float2*)&Ps[(qw + g) * PSTR + nt * 8 + 2 * t]     = make_float2(p0, p1);
            *(float2*)&Ps[(qw + g + 8) * PSTR + nt * 8 + 2 * t] = make_float2(p2, p3);
        }
        sum0 += __shfl_xor_sync(0xffffffffu, sum0, 1);
        sum0 += __shfl_xor_sync(0xffffffffu, sum0, 2);
        sum1 += __shfl_xor_sync(0xffffffffu, sum1, 1);
        sum1 += __shfl_xor_sync(0xffffffffu, sum1, 2);
        l0 = l0 * alpha0 + sum0;  m0 = mn0;
        l1 = l1 * alpha1 + sum1;  m1 = mn1;

#pragma unroll
        for (int nt = 0; nt < 16; ++nt) {
            O[nt][0] *= alpha0; O[nt][1] *= alpha0;
            O[nt][2] *= alpha1; O[nt][3] *= alpha1;
        }

        // ---- PV: O m16 x n128, k=64  (Ps is warp-private: no block sync needed)
        __syncwarp();
#pragma unroll
        for (int kf = 0; kf < 8; ++kf) {
            unsigned ap[4];
            const float* pp = Ps + (qw + g) * PSTR + kf * 8 + t;
            ap[0] = __float_as_uint(pp[0]);
            ap[1] = __float_as_uint(pp[8 * PSTR]);
            ap[2] = __float_as_uint(pp[4]);
            ap[3] = __float_as_uint(pp[8 * PSTR + 4]);
#pragma unroll
            for (int nt = 0; nt < 16; ++nt) {
                unsigned bf[2];
                const float* vp = VsS + (kf * 8 + t) * VSTR + nt * 8 + g;
                bf[0] = __float_as_uint(vp[0]);
                bf[1] = __float_as_uint(vp[4 * VSTR]);
                mma_tf32(O[nt], ap, bf);
            }
        }
        __syncthreads();   // all warps done with this stage's K/V before reuse
        st ^= 1;
    }

    // ---- epilogue
    const float inv0 = 1.f / l0;
    const float inv1 = 1.f / l1;
    float* op0 = g_attn + (size_t)(b * CS + qg0) * 1024 + h * 128;
    float* op1 = g_attn + (size_t)(b * CS + qg1) * 1024 + h * 128;
#pragma unroll
    for (int nt = 0; nt < 16; ++nt) {
        *(float2*)(op0 + nt * 8 + 2 * t) = make_float2(O[nt][0] * inv0, O[nt][1] * inv0);
        *(float2*)(op1 + nt * 8 + 2 * t) = make_float2(O[nt][2] * inv1, O[nt][3] * inv1);
    }
}

// ---------------------------------------------------------------------------
extern "C" void kernel_launch(void* const* d_in, const int* in_sizes, int n_in,
                              void* d_out, int out_size)
{
    const float* hidden = (const float*)d_in[0];
    const float* Wq     = (const float*)d_in[1];
    const float* Wk     = (const float*)d_in[2];
    const float* Wv     = (const float*)d_in[3];
    const float* Wdt    = (const float*)d_in[4];
    const float* Aw     = (const float*)d_in[5];
    const float* Wo     = (const float*)d_in[6];
    const float* cosb   = (const float*)d_in[7];
    const float* sinb   = (const float*)d_in[8];
    float* out = (float*)d_out;

    cudaFuncSetAttribute(k_qkv_tc,  cudaFuncAttributeMaxDynamicSharedMemorySize, GEMM_SMEM_BYTES);
    cudaFuncSetAttribute(k_out_tc,  cudaFuncAttributeMaxDynamicSharedMemorySize, GEMM_SMEM_BYTES);
    cudaFuncSetAttribute(k_attn_tc, cudaFuncAttributeMaxDynamicSharedMemorySize, ATTN_TC_BYTES);

    k_qkv_tc<<<dim3(16, 32), 256, GEMM_SMEM_BYTES>>>(hidden, Wq, Wk, Wv);
    k_rope<<<(CBS * 12 * 64 + 255) / 256, 256>>>(cosb, sinb);
    k_biask<<<CBS / 8, 256>>>(Wdt, Aw);
    k_attn_tc<<<dim3(16, 16), 256, ATTN_TC_BYTES>>>();
    k_out_tc<<<dim3(8, 32), 256, GEMM_SMEM_BYTES>>>(Wo, out);
}

// round 7
// speedup vs baseline: 1.6840x; 1.4612x over previous
#include <cuda_runtime.h>
#include <math.h>

// Problem constants
#define CB 2
#define CS 2048
#define CHID 1024
#define CH 8
#define CKV 4
#define CD 128
#define CBS (CB * CS)                 // 4096 rows
#define CSCALE 0.08838834764831845f   // 128^-0.5

// Scratch (allocation-free rule: __device__ globals)
__device__ float g_q[CBS * CH * CD];      // rope'd, tf32-RNA rounded
__device__ float g_k[CBS * CKV * CD];     // rope'd, tf32-RNA rounded
__device__ float g_v[CBS * CKV * CD];     // tf32-RNA rounded at qkv epilogue
__device__ float g_biasT[CH * CB * CS];   // dyn transposed: [h][b][s]
__device__ float g_attn[CBS * CH * CD];   // attention output

__device__ __forceinline__ void cp16(unsigned dst, const void* src) {
    asm volatile("cp.async.cg.shared.global [%0], [%1], 16;\n" :: "r"(dst), "l"(src));
}

__device__ __forceinline__ unsigned f2tf32(float x) {
    unsigned r;
    asm("cvt.rna.tf32.f32 %0, %1;\n" : "=r"(r) : "f"(x));
    return r;
}
__device__ __forceinline__ float tf32r(float x) { return __uint_as_float(f2tf32(x)); }

__device__ __forceinline__ unsigned tf32_split(float x, unsigned& lo) {
    const unsigned hi = f2tf32(x);
    lo = f2tf32(x - __uint_as_float(hi));
    return hi;
}

__device__ __forceinline__ void mma_tf32(float* d, const unsigned* a, const unsigned* b) {
    asm volatile(
        "mma.sync.aligned.m16n8k8.row.col.f32.tf32.tf32.f32 "
        "{%0,%1,%2,%3}, {%4,%5,%6,%7}, {%8,%9}, {%0,%1,%2,%3};\n"
        : "+f"(d[0]), "+f"(d[1]), "+f"(d[2]), "+f"(d[3])
        : "r"(a[0]), "r"(a[1]), "r"(a[2]), "r"(a[3]), "r"(b[0]), "r"(b[1]));
}

// ===========================================================================
// 3xTF32 projection GEMM (proven passing; rel_err contribution ~1.6e-5)
// ===========================================================================
#define GEMM_SMEM_FLOATS (2 * 128 * 36 + 2 * 32 * 132)
#define GEMM_SMEM_BYTES (GEMM_SMEM_FLOATS * 4)

__device__ __forceinline__ void gemm128_3xtf32(
    const float* __restrict__ A, int lda,
    const float* __restrict__ B, int ldb,
    float* __restrict__ C, int ldc, bool roundC)
{
    extern __shared__ float sm[];
    float* As = sm;                 // [2][128*36]
    float* Bs = sm + 2 * 4608;      // [2][32*132]
    const unsigned asBase = (unsigned)__cvta_generic_to_shared(As);
    const unsigned bsBase = (unsigned)__cvta_generic_to_shared(Bs);

    const int tid = threadIdx.x;
    const int w = tid >> 5, lane = tid & 31;
    const int g = lane >> 2, t = lane & 3;
    const int rb = (w >> 2) * 64;
    const int cb = (w & 3) * 32;

    float acc[4][4][4];
#pragma unroll
    for (int mt = 0; mt < 4; ++mt)
#pragma unroll
        for (int nt = 0; nt < 4; ++nt)
#pragma unroll
            for (int r = 0; r < 4; ++r) acc[mt][nt][r] = 0.f;

    auto issue = [&](int k0, int s) {
#pragma unroll
        for (int i = 0; i < 4; ++i) {
            const int idx = tid + i * 256;
            const int r = idx >> 3, c = (idx & 7) << 2;
            cp16(asBase + (unsigned)((s * 4608 + r * 36 + c) << 2),
                 A + (size_t)r * lda + k0 + c);
        }
#pragma unroll
        for (int i = 0; i < 4; ++i) {
            const int idx = tid + i * 256;
            const int r = idx >> 5, c = (idx & 31) << 2;
            cp16(bsBase + (unsigned)((s * 4224 + r * 132 + c) << 2),
                 B + (size_t)(k0 + r) * ldb + c);
        }
        asm volatile("cp.async.commit_group;\n");
    };

    issue(0, 0);
    int s = 0;
    for (int k0 = 0; k0 < 1024; k0 += 32) {
        asm volatile("cp.async.wait_group 0;\n");
        __syncthreads();
        if (k0 + 32 < 1024) issue(k0 + 32, s ^ 1);
        const float* AsS = As + s * 4608;
        const float* BsS = Bs + s * 4224;
#pragma unroll
        for (int ks = 0; ks < 4; ++ks) {
            const int kk = ks * 8;
            unsigned ah[4][4], al[4][4], bh[4][2], bl[4][2];
#pragma unroll
            for (int mt = 0; mt < 4; ++mt) {
                const float* p = AsS + (rb + mt * 16 + g) * 36 + kk + t;
                ah[mt][0] = tf32_split(p[0],          al[mt][0]);
                ah[mt][1] = tf32_split(p[8 * 36],     al[mt][1]);
                ah[mt][2] = tf32_split(p[4],          al[mt][2]);
                ah[mt][3] = tf32_split(p[8 * 36 + 4], al[mt][3]);
            }
#pragma unroll
            for (int nt = 0; nt < 4; ++nt) {
                const float* p = BsS + (kk + t) * 132 + cb + nt * 8 + g;
                bh[nt][0] = tf32_split(p[0],       bl[nt][0]);
                bh[nt][1] = tf32_split(p[4 * 132], bl[nt][1]);
            }
#pragma unroll
            for (int mt = 0; mt < 4; ++mt)
#pragma unroll
                for (int nt = 0; nt < 4; ++nt) {
                    mma_tf32(acc[mt][nt], al[mt], bh[nt]);
                    mma_tf32(acc[mt][nt], ah[mt], bl[nt]);
                    mma_tf32(acc[mt][nt], ah[mt], bh[nt]);
                }
        }
        s ^= 1;
    }

#pragma unroll
    for (int mt = 0; mt < 4; ++mt)
#pragma unroll
        for (int nt = 0; nt < 4; ++nt) {
            const int r0 = rb + mt * 16 + g;
            const int c0 = cb + nt * 8 + 2 * t;
            float v0 = acc[mt][nt][0], v1 = acc[mt][nt][1];
            float v2 = acc[mt][nt][2], v3 = acc[mt][nt][3];
            if (roundC) { v0 = tf32r(v0); v1 = tf32r(v1); v2 = tf32r(v2); v3 = tf32r(v3); }
            *(float2*)(C + (size_t)r0 * ldc + c0)       = make_float2(v0, v1);
            *(float2*)(C + (size_t)(r0 + 8) * ldc + c0) = make_float2(v2, v3);
        }
}

// Kernel 1: fused QKV projection; V output rounded to tf32 (PV exactness)
__global__ void __launch_bounds__(256) k_qkv_tc(
    const float* __restrict__ hidden,
    const float* __restrict__ Wq,
    const float* __restrict__ Wk,
    const float* __restrict__ Wv)
{
    const int n0 = blockIdx.x * 128;
    const int m0 = blockIdx.y * 128;
    const float* A = hidden + (size_t)m0 * CHID;
    if (n0 < 1024)
        gemm128_3xtf32(A, CHID, Wq + n0, 1024, g_q + (size_t)m0 * 1024 + n0, 1024, false);
    else if (n0 < 1536)
        gemm128_3xtf32(A, CHID, Wk + (n0 - 1024), 512, g_k + (size_t)m0 * 512 + (n0 - 1024), 512, false);
    else
        gemm128_3xtf32(A, CHID, Wv + (n0 - 1536), 512, g_v + (size_t)m0 * 512 + (n0 - 1536), 512, true);
}

// Kernel 5: output projection
__global__ void __launch_bounds__(256) k_out_tc(
    const float* __restrict__ Wo, float* __restrict__ out)
{
    const int n0 = blockIdx.x * 128;
    const int m0 = blockIdx.y * 128;
    gemm128_3xtf32(g_attn + (size_t)m0 * 1024, 1024, Wo + n0, 1024,
                   out + (size_t)m0 * 1024 + n0, 1024, false);
}

// ---------------------------------------------------------------------------
// Kernel 2: RoPE on q and k -- writes tf32-RNA-rounded values (QK exactness)
// ---------------------------------------------------------------------------
__global__ void k_rope(const float* __restrict__ cosb, const float* __restrict__ sinb)
{
    const int t = blockIdx.x * blockDim.x + threadIdx.x;
    const int total = CBS * 12 * 64;
    if (t >= total) return;
    const int d = t & 63;
    const int head = (t >> 6) % 12;
    const int row = t / (12 * 64);
    const int s = row & (CS - 1);
    const float c1  = cosb[s * CD + d];
    const float sn1 = sinb[s * CD + d];
    const float c2  = cosb[s * CD + d + 64];
    const float sn2 = sinb[s * CD + d + 64];
    float* p;
    if (head < CH) p = g_q + (size_t)row * (CH * CD) + head * CD;
    else           p = g_k + (size_t)row * (CKV * CD) + (head - CH) * CD;
    const float x1 = p[d], x2 = p[d + 64];
    p[d]      = tf32r(x1 * c1 - x2 * sn1);
    p[d + 64] = tf32r(x2 * c2 + x1 * sn2);
}

// ---------------------------------------------------------------------------
// Kernel 3: dt = v_flat @ Wdt ; dyn = exp(A * softplus(dt)) -> g_biasT [h][b][s]
// ---------------------------------------------------------------------------
__global__ void __launch_bounds__(256) k_biask(
    const float* __restrict__ Wdt, const float* __restrict__ Aw)
{
    __shared__ float sW[512 * 8];
    for (int i = threadIdx.x; i < 512 * 8; i += 256) sW[i] = Wdt[i];
    __syncthreads();
    const int warp = threadIdx.x >> 5;
    const int lane = threadIdx.x & 31;
    const int row = blockIdx.x * 8 + warp;
    const float* vrow = g_v + (size_t)row * 512;
    float acc[8];
#pragma unroll
    for (int h = 0; h < 8; ++h) acc[h] = 0.f;
    for (int j = lane; j < 512; j += 32) {
        const float vv = vrow[j];
#pragma unroll
        for (int h = 0; h < 8; ++h) acc[h] = fmaf(vv, sW[j * 8 + h], acc[h]);
    }
#pragma unroll
    for (int off = 16; off > 0; off >>= 1)
#pragma unroll
        for (int h = 0; h < 8; ++h)
            acc[h] += __shfl_xor_sync(0xffffffffu, acc[h], off);
    if (lane < 8) {
        const float dt = acc[lane];
        const float sp = (dt > 20.f) ? dt : log1pf(expf(dt));
        const int b = row >> 11;
        const int s = row & (CS - 1);
        g_biasT[(size_t)(lane * CB + b) * CS + s] = expf(Aw[lane] * sp);
    }
}

// ===========================================================================
// Kernel 4: causal flash attention, tf32 mma; all mma inputs RNA-pre-rounded
// ===========================================================================
#define KSTR 132
#define VSTR 136
#define PST 68
#define AT_KS 0
#define AT_VS (2 * 64 * KSTR)
#define AT_PS (AT_VS + 2 * 64 * VSTR)
#define AT_BIAS (AT_PS + 128 * PST)
#define ATTN_TC_FLOATS (AT_BIAS + 2 * 64)
#define ATTN_TC_BYTES (ATTN_TC_FLOATS * 4)

__global__ void __launch_bounds__(256, 1) k_attn_tc()
{
    extern __shared__ float sm[];
    float* Ks = sm + AT_KS;
    float* Vs = sm + AT_VS;
    float* Ps = sm + AT_PS;
    float* bias_s = sm + AT_BIAS;
    const unsigned smBase = (unsigned)__cvta_generic_to_shared(sm);

    const int tid = threadIdx.x;
    const int w = tid >> 5, lane = tid & 31;
    const int g = lane >> 2, t = lane & 3;
    const int bh = blockIdx.x;
    const int b = bh >> 3;
    const int h = bh & 7;
    const int kvh = h >> 1;
    const int qt = (int)gridDim.y - 1 - (int)blockIdx.y;
    const int q0 = qt * 128;
    const int qw = w * 16;
    const int qg0 = q0 + qw + g;
    const int qg1 = qg0 + 8;

    unsigned aq[16][4];
    {
        const float* qp = g_q + (size_t)(b * CS + qg0) * 1024 + h * 128;
#pragma unroll
        for (int kf = 0; kf < 16; ++kf) {
            aq[kf][0] = __float_as_uint(qp[kf * 8 + t]);
            aq[kf][1] = __float_as_uint(qp[8 * 1024 + kf * 8 + t]);
            aq[kf][2] = __float_as_uint(qp[kf * 8 + t + 4]);
            aq[kf][3] = __float_as_uint(qp[8 * 1024 + kf * 8 + t + 4]);
        }
    }

    float O[16][4];
#pragma unroll
    for (int nt = 0; nt < 16; ++nt)
#pragma unroll
        for (int r = 0; r < 4; ++r) O[nt][r] = 0.f;
    float m0 = -1e30f, m1 = -1e30f, l0 = 0.f, l1 = 0.f;

    const int nkt = 2 * qt + 2;

    auto issue = [&](int kt, int st) {
        const int kbase = kt * 64;
#pragma unroll
        for (int i = 0; i < 8; ++i) {
            const int idx = tid + i * 256;
            const int c = idx >> 5, dc = (idx & 31) << 2;
            const size_t grow = (size_t)(b * CS + kbase + c) * 512 + kvh * 128 + dc;
            cp16(smBase + (unsigned)((AT_KS + st * 64 * KSTR + c * KSTR + dc) << 2), g_k + grow);
            cp16(smBase + (unsigned)((AT_VS + st * 64 * VSTR + c * VSTR + dc) << 2), g_v + grow);
        }
        if (tid < 16)
            cp16(smBase + (unsigned)((AT_BIAS + st * 64 + tid * 4) << 2),
                 g_biasT + (size_t)(h * CB + b) * CS + kbase + tid * 4);
        asm volatile("cp.async.commit_group;\n");
    };

    issue(0, 0);
    int st = 0;
    for (int kt = 0; kt < nkt; ++kt) {
        const int kbase = kt * 64;
        asm volatile("cp.async.wait_group 0;\n");
        __syncthreads();
        if (kt + 1 < nkt) issue(kt + 1, st ^ 1);

        const float* KsS = Ks + st * 64 * KSTR;
        const float* VsS = Vs + st * 64 * VSTR;
        const float* biasS = bias_s + st * 64;

        float sacc[8][4];
#pragma unroll
        for (int nt = 0; nt < 8; ++nt)
#pragma unroll
            for (int r = 0; r < 4; ++r) sacc[nt][r] = 0.f;
#pragma unroll
        for (int kf = 0; kf < 16; ++kf) {
#pragma unroll
            for (int nt = 0; nt < 8; ++nt) {
                unsigned bf[2];
                const float* kp = KsS + (nt * 8 + g) * KSTR + kf * 8 + t;
                bf[0] = __float_as_uint(kp[0]);
                bf[1] = __float_as_uint(kp[4]);
                mma_tf32(sacc[nt], aq[kf], bf);
            }
        }

        float mx0 = -1e30f, mx1 = -1e30f;
#pragma unroll
        for (int nt = 0; nt < 8; ++nt) {
            const int kg = kbase + nt * 8 + 2 * t;
            const float b0 = biasS[nt * 8 + 2 * t];
            const float b1 = biasS[nt * 8 + 2 * t + 1];
            sacc[nt][0] = (kg     <= qg0) ? fmaf(sacc[nt][0], CSCALE, b0) : -1e30f;
            sacc[nt][1] = (kg + 1 <= qg0) ? fmaf(sacc[nt][1], CSCALE, b1) : -1e30f;
            sacc[nt][2] = (kg     <= qg1) ? fmaf(sacc[nt][2], CSCALE, b0) : -1e30f;
            sacc[nt][3] = (kg + 1 <= qg1) ? fmaf(sacc[nt][3], CSCALE, b1) : -1e30f;
            mx0 = fmaxf(mx0, fmaxf(sacc[nt][0], sacc[nt][1]));
            mx1 = fmaxf(mx1, fmaxf(sacc[nt][2], sacc[nt][3]));
        }
        mx0 = fmaxf(mx0, __shfl_xor_sync(0xffffffffu, mx0, 1));
        mx0 = fmaxf(mx0, __shfl_xor_sync(0xffffffffu, mx0, 2));
        mx1 = fmaxf(mx1, __shfl_xor_sync(0xffffffffu, mx1, 1));
        mx1 = fmaxf(mx1, __shfl_xor_sync(0xffffffffu, mx1, 2));

        const float mn0 = fmaxf(m0, mx0);
        const float mn1 = fmaxf(m1, mx1);
        const float alpha0 = __expf(m0 - mn0);
        const float alpha1 = __expf(m1 - mn1);
        float sum0 = 0.f, sum1 = 0.f;
#pragma unroll
        for (int nt = 0; nt < 8; ++nt) {
            // round p once (RNA); same p feeds l-sum and PV -> consistent O/l
            const float p0 = tf32r(__expf(sacc[nt][0] - mn0));
            const float p1 = tf32r(__expf(sacc[nt][1] - mn0));
            const float p2 = tf32r(__expf(sacc[nt][2] - mn1));
            const float p3 = tf32r(__expf(sacc[nt][3] - mn1));
            sum0 += p0 + p1;
            sum1 += p2 + p3;
            *(float2*)&Ps[(qw + g) * PST + nt * 8 + 2 * t]     = make_float2(p0, p1);
            *(float2*)&Ps[(qw + g + 8) * PST + nt * 8 + 2 * t] = make_float2(p2, p3);
        }
        sum0 += __shfl_xor_sync(0xffffffffu, sum0, 1);
        sum0 += __shfl_xor_sync(0xffffffffu, sum0, 2);
        sum1 += __shfl_xor_sync(0xffffffffu, sum1, 1);
        sum1 += __shfl_xor_sync(0xffffffffu, sum1, 2);
        l0 = l0 * alpha0 + sum0;  m0 = mn0;
        l1 = l1 * alpha1 + sum1;  m1 = mn1;

#pragma unroll
        for (int nt = 0; nt < 16; ++nt) {
            O[nt][0] *= alpha0; O[nt][1] *= alpha0;
            O[nt][2] *= alpha1; O[nt][3] *= alpha1;
        }

        __syncwarp();
#pragma unroll
        for (int kf = 0; kf < 8; ++kf) {
            unsigned ap[4];
            const float* pp = Ps + (qw + g) * PST + kf * 8 + t;
            ap[0] = __float_as_uint(pp[0]);
            ap[1] = __float_as_uint(pp[8 * PST]);
            ap[2] = __float_as_uint(pp[4]);
            ap[3] = __float_as_uint(pp[8 * PST + 4]);
#pragma unroll
            for (int nt = 0; nt < 16; ++nt) {
                unsigned bf[2];
                const float* vp = VsS + (kf * 8 + t) * VSTR + nt * 8 + g;
                bf[0] = __float_as_uint(vp[0]);
                bf[1] = __float_as_uint(vp[4 * VSTR]);
                mma_tf32(O[nt], ap, bf);
            }
        }
        __syncthreads();
        st ^= 1;
    }

    const float inv0 = 1.f / l0;
    const float inv1 = 1.f / l1;
    float* op0 = g_attn + (size_t)(b * CS + qg0) * 1024 + h * 128;
    float* op1 = g_attn + (size_t)(b * CS + qg1) * 1024 + h * 128;
#pragma unroll
    for (int nt = 0; nt < 16; ++nt) {
        *(float2*)(op0 + nt * 8 + 2 * t) = make_float2(O[nt][0] * inv0, O[nt][1] * inv0);
        *(float2*)(op1 + nt * 8 + 2 * t) = make_float2(O[nt][2] * inv1, O[nt][3] * inv1);
    }
}

// ---------------------------------------------------------------------------
extern "C" void kernel_launch(void* const* d_in, const int* in_sizes, int n_in,
                              void* d_out, int out_size)
{
    const float* hidden = (const float*)d_in[0];
    const float* Wq     = (const float*)d_in[1];
    const float* Wk     = (const float*)d_in[2];
    const float* Wv     = (const float*)d_in[3];
    const float* Wdt    = (const float*)d_in[4];
    const float* Aw     = (const float*)d_in[5];
    const float* Wo     = (const float*)d_in[6];
    const float* cosb   = (const float*)d_in[7];
    const float* sinb   = (const float*)d_in[8];
    float* out = (float*)d_out;

    cudaFuncSetAttribute(k_qkv_tc,  cudaFuncAttributeMaxDynamicSharedMemorySize, GEMM_SMEM_BYTES);
    cudaFuncSetAttribute(k_out_tc,  cudaFuncAttributeMaxDynamicSharedMemorySize, GEMM_SMEM_BYTES);
    cudaFuncSetAttribute(k_attn_tc, cudaFuncAttributeMaxDynamicSharedMemorySize, ATTN_TC_BYTES);

    k_qkv_tc<<<dim3(16, 32), 256, GEMM_SMEM_BYTES>>>(hidden, Wq, Wk, Wv);
    k_rope<<<(CBS * 12 * 64 + 255) / 256, 256>>>(cosb, sinb);
    k_biask<<<CBS / 8, 256>>>(Wdt, Aw);
    k_attn_tc<<<dim3(16, 16), 256, ATTN_TC_BYTES>>>();
    k_out_tc<<<dim3(8, 32), 256, GEMM_SMEM_BYTES>>>(Wo, out);
}

// round 9
// speedup vs baseline: 1.7208x; 1.0219x over previous
#include <cuda_runtime.h>
#include <math.h>

// Problem constants
#define CB 2
#define CS 2048
#define CHID 1024
#define CH 8
#define CKV 4
#define CD 128
#define CBS (CB * CS)                 // 4096 rows
#define CSCALE 0.08838834764831845f   // 128^-0.5

// Scratch (allocation-free rule: __device__ globals)
__device__ float g_q[CBS * CH * CD];      // rope'd, tf32-RNA rounded
__device__ float g_k[CBS * CKV * CD];     // rope'd, tf32-RNA rounded
__device__ float g_v[CBS * CKV * CD];     // tf32-RNA rounded at qkv epilogue
__device__ float g_biasT[CH * CB * CS];   // dyn transposed: [h][b][s]

// Precomputed tf32 hi/lo operand arrays (split hoisted out of the GEMMs)
__device__ float g_hid_hi[CBS * CHID],  g_hid_lo[CBS * CHID];   // [row][k]
__device__ float g_wq_hi[CHID * 1024],  g_wq_lo[CHID * 1024];   // [k][n]
__device__ float g_wk_hi[CHID * 512],   g_wk_lo[CHID * 512];
__device__ float g_wv_hi[CHID * 512],   g_wv_lo[CHID * 512];
__device__ float g_wo_hi[1024 * CHID],  g_wo_lo[1024 * CHID];
__device__ float g_at_hi[CBS * 1024],   g_at_lo[CBS * 1024];    // attn out split

__device__ __forceinline__ void cp16(unsigned dst, const void* src) {
    asm volatile("cp.async.cg.shared.global [%0], [%1], 16;\n" :: "r"(dst), "l"(src));
}

__device__ __forceinline__ unsigned f2tf32(float x) {
    unsigned r;
    asm("cvt.rna.tf32.f32 %0, %1;\n" : "=r"(r) : "f"(x));
    return r;
}
__device__ __forceinline__ float tf32r(float x) { return __uint_as_float(f2tf32(x)); }

__device__ __forceinline__ void mma_tf32(float* d, const unsigned* a, const unsigned* b) {
    asm volatile(
        "mma.sync.aligned.m16n8k8.row.col.f32.tf32.tf32.f32 "
        "{%0,%1,%2,%3}, {%4,%5,%6,%7}, {%8,%9}, {%0,%1,%2,%3};\n"
        : "+f"(d[0]), "+f"(d[1]), "+f"(d[2]), "+f"(d[3])
        : "r"(a[0]), "r"(a[1]), "r"(a[2]), "r"(a[3]), "r"(b[0]), "r"(b[1]));
}

// ---------------------------------------------------------------------------
// Elementwise tf32 hi/lo split (float4-vectorized).
// DESTINATION SELECTED IN DEVICE CODE (int tag) — a __device__ symbol passed
// from host code resolves to the host shadow (ATS-reachable on GB300!), which
// was the round-6/8 silent-zero bug.
// ---------------------------------------------------------------------------
__global__ void k_cvt4(const float* __restrict__ src, int which, int n4)
{
    const int idx = blockIdx.x * blockDim.x + threadIdx.x;
    if (idx >= n4) return;
    float* hi; float* lo;
    switch (which) {
        case 0: hi = g_hid_hi; lo = g_hid_lo; break;
        case 1: hi = g_wq_hi;  lo = g_wq_lo;  break;
        case 2: hi = g_wk_hi;  lo = g_wk_lo;  break;
        case 3: hi = g_wv_hi;  lo = g_wv_lo;  break;
        default: hi = g_wo_hi; lo = g_wo_lo;  break;
    }
    const float4 v = ((const float4*)src)[idx];
    float4 h, l;
    h.x = tf32r(v.x); l.x = tf32r(v.x - h.x);
    h.y = tf32r(v.y); l.y = tf32r(v.y - h.y);
    h.z = tf32r(v.z); l.z = tf32r(v.z - h.z);
    h.w = tf32r(v.w); l.w = tf32r(v.w - h.w);
    ((float4*)hi)[idx] = h;
    ((float4*)lo)[idx] = l;
}

// ===========================================================================
// 3xTF32 GEMM with PRE-SPLIT operands: C[128,128] = A[128,1024] @ B[1024,128]
// 8 warps (2Mx4N), warp 64x32, m16n8k8. Inner loop: pure LDS -> mma (no cvt).
// ===========================================================================
#define AH_OFF 0
#define AL_OFF (2 * 4608)             // 9216
#define BH_OFF (4 * 4608)             // 18432
#define BL_OFF (BH_OFF + 2 * 4224)    // 26880
#define GEMM_SMEM_FLOATS (BL_OFF + 2 * 4224)   // 35328
#define GEMM_SMEM_BYTES (GEMM_SMEM_FLOATS * 4) // 141312

__device__ __forceinline__ void gemm128_presplit(
    const float* __restrict__ Ahi, const float* __restrict__ Alo,
    const float* __restrict__ Bhi, const float* __restrict__ Blo,
    int ldb, float* __restrict__ C, int ldc, bool roundC)
{
    extern __shared__ float sm[];
    const unsigned smBase = (unsigned)__cvta_generic_to_shared(sm);

    const int tid = threadIdx.x;
    const int w = tid >> 5, lane = tid & 31;
    const int g = lane >> 2, t = lane & 3;
    const int rb = (w >> 2) * 64;
    const int cb = (w & 3) * 32;

    float acc[4][4][4];
#pragma unroll
    for (int mt = 0; mt < 4; ++mt)
#pragma unroll
        for (int nt = 0; nt < 4; ++nt)
#pragma unroll
            for (int r = 0; r < 4; ++r) acc[mt][nt][r] = 0.f;

    auto issue = [&](int k0, int s) {
#pragma unroll
        for (int i = 0; i < 4; ++i) {
            const int idx = tid + i * 256;
            const int r = idx >> 3, c = (idx & 7) << 2;
            const size_t go = (size_t)r * CHID + k0 + c;
            cp16(smBase + (unsigned)((AH_OFF + s * 4608 + r * 36 + c) << 2), Ahi + go);
            cp16(smBase + (unsigned)((AL_OFF + s * 4608 + r * 36 + c) << 2), Alo + go);
        }
#pragma unroll
        for (int i = 0; i < 4; ++i) {
            const int idx = tid + i * 256;
            const int r = idx >> 5, c = (idx & 31) << 2;
            const size_t go = (size_t)(k0 + r) * ldb + c;
            cp16(smBase + (unsigned)((BH_OFF + s * 4224 + r * 132 + c) << 2), Bhi + go);
            cp16(smBase + (unsigned)((BL_OFF + s * 4224 + r * 132 + c) << 2), Blo + go);
        }
        asm volatile("cp.async.commit_group;\n");
    };

    issue(0, 0);
    int s = 0;
    for (int k0 = 0; k0 < 1024; k0 += 32) {
        asm volatile("cp.async.wait_group 0;\n");
        __syncthreads();
        if (k0 + 32 < 1024) issue(k0 + 32, s ^ 1);
        const float* AH = sm + AH_OFF + s * 4608;
        const float* AL = sm + AL_OFF + s * 4608;
        const float* BH = sm + BH_OFF + s * 4224;
        const float* BL = sm + BL_OFF + s * 4224;
#pragma unroll
        for (int ks = 0; ks < 4; ++ks) {
            const int kk = ks * 8;
            unsigned ah[4][4], al[4][4], bh[4][2], bl[4][2];
#pragma unroll
            for (int mt = 0; mt < 4; ++mt) {
                const int ro = (rb + mt * 16 + g) * 36 + kk + t;
                ah[mt][0] = __float_as_uint(AH[ro]);
                ah[mt][1] = __float_as_uint(AH[ro + 8 * 36]);
                ah[mt][2] = __float_as_uint(AH[ro + 4]);
                ah[mt][3] = __float_as_uint(AH[ro + 8 * 36 + 4]);
                al[mt][0] = __float_as_uint(AL[ro]);
                al[mt][1] = __float_as_uint(AL[ro + 8 * 36]);
                al[mt][2] = __float_as_uint(AL[ro + 4]);
                al[mt][3] = __float_as_uint(AL[ro + 8 * 36 + 4]);
            }
#pragma unroll
            for (int nt = 0; nt < 4; ++nt) {
                const int co = (kk + t) * 132 + cb + nt * 8 + g;
                bh[nt][0] = __float_as_uint(BH[co]);
                bh[nt][1] = __float_as_uint(BH[co + 4 * 132]);
                bl[nt][0] = __float_as_uint(BL[co]);
                bl[nt][1] = __float_as_uint(BL[co + 4 * 132]);
            }
#pragma unroll
            for (int mt = 0; mt < 4; ++mt)
#pragma unroll
                for (int nt = 0; nt < 4; ++nt) {
                    mma_tf32(acc[mt][nt], al[mt], bh[nt]);
                    mma_tf32(acc[mt][nt], ah[mt], bl[nt]);
                    mma_tf32(acc[mt][nt], ah[mt], bh[nt]);
                }
        }
        s ^= 1;
    }

#pragma unroll
    for (int mt = 0; mt < 4; ++mt)
#pragma unroll
        for (int nt = 0; nt < 4; ++nt) {
            const int r0 = rb + mt * 16 + g;
            const int c0 = cb + nt * 8 + 2 * t;
            float v0 = acc[mt][nt][0], v1 = acc[mt][nt][1];
            float v2 = acc[mt][nt][2], v3 = acc[mt][nt][3];
            if (roundC) { v0 = tf32r(v0); v1 = tf32r(v1); v2 = tf32r(v2); v3 = tf32r(v3); }
            *(float2*)(C + (size_t)r0 * ldc + c0)       = make_float2(v0, v1);
            *(float2*)(C + (size_t)(r0 + 8) * ldc + c0) = make_float2(v2, v3);
        }
}

// Kernel 1: fused QKV projection; V output rounded to tf32 (PV exactness)
__global__ void __launch_bounds__(256) k_qkv_tc()
{
    const int n0 = blockIdx.x * 128;
    const int m0 = blockIdx.y * 128;
    const float* Ah = g_hid_hi + (size_t)m0 * CHID;
    const float* Al = g_hid_lo + (size_t)m0 * CHID;
    if (n0 < 1024)
        gemm128_presplit(Ah, Al, g_wq_hi + n0, g_wq_lo + n0, 1024,
                         g_q + (size_t)m0 * 1024 + n0, 1024, false);
    else if (n0 < 1536)
        gemm128_presplit(Ah, Al, g_wk_hi + (n0 - 1024), g_wk_lo + (n0 - 1024), 512,
                         g_k + (size_t)m0 * 512 + (n0 - 1024), 512, false);
    else
        gemm128_presplit(Ah, Al, g_wv_hi + (n0 - 1536), g_wv_lo + (n0 - 1536), 512,
                         g_v + (size_t)m0 * 512 + (n0 - 1536), 512, true);
}

// Kernel 5: output projection (A = pre-split attention output)
__global__ void __launch_bounds__(256) k_out_tc(float* __restrict__ out)
{
    const int n0 = blockIdx.x * 128;
    const int m0 = blockIdx.y * 128;
    gemm128_presplit(g_at_hi + (size_t)m0 * 1024, g_at_lo + (size_t)m0 * 1024,
                     g_wo_hi + n0, g_wo_lo + n0, 1024,
                     out + (size_t)m0 * 1024 + n0, 1024, false);
}

// ---------------------------------------------------------------------------
// Kernel 2: RoPE on q and k -- writes tf32-RNA-rounded values (QK exactness)
// ---------------------------------------------------------------------------
__global__ void k_rope(const float* __restrict__ cosb, const float* __restrict__ sinb)
{
    const int t = blockIdx.x * blockDim.x + threadIdx.x;
    const int total = CBS * 12 * 64;
    if (t >= total) return;
    const int d = t & 63;
    const int head = (t >> 6) % 12;
    const int row = t / (12 * 64);
    const int s = row & (CS - 1);
    const float c1  = cosb[s * CD + d];
    const float sn1 = sinb[s * CD + d];
    const float c2  = cosb[s * CD + d + 64];
    const float sn2 = sinb[s * CD + d + 64];
    float* p;
    if (head < CH) p = g_q + (size_t)row * (CH * CD) + head * CD;
    else           p = g_k + (size_t)row * (CKV * CD) + (head - CH) * CD;
    const float x1 = p[d], x2 = p[d + 64];
    p[d]      = tf32r(x1 * c1 - x2 * sn1);
    p[d + 64] = tf32r(x2 * c2 + x1 * sn2);
}

// ---------------------------------------------------------------------------
// Kernel 3: dt = v_flat @ Wdt ; dyn = exp(A * softplus(dt)) -> g_biasT [h][b][s]
// ---------------------------------------------------------------------------
__global__ void __launch_bounds__(256) k_biask(
    const float* __restrict__ Wdt, const float* __restrict__ Aw)
{
    __shared__ float sW[512 * 8];
    for (int i = threadIdx.x; i < 512 * 8; i += 256) sW[i] = Wdt[i];
    __syncthreads();
    const int warp = threadIdx.x >> 5;
    const int lane = threadIdx.x & 31;
    const int row = blockIdx.x * 8 + warp;
    const float* vrow = g_v + (size_t)row * 512;
    float acc[8];
#pragma unroll
    for (int h = 0; h < 8; ++h) acc[h] = 0.f;
    for (int j = lane; j < 512; j += 32) {
        const float vv = vrow[j];
#pragma unroll
        for (int h = 0; h < 8; ++h) acc[h] = fmaf(vv, sW[j * 8 + h], acc[h]);
    }
#pragma unroll
    for (int off = 16; off > 0; off >>= 1)
#pragma unroll
        for (int h = 0; h < 8; ++h)
            acc[h] += __shfl_xor_sync(0xffffffffu, acc[h], off);
    if (lane < 8) {
        const float dt = acc[lane];
        const float sp = (dt > 20.f) ? dt : log1pf(expf(dt));
        const int b = row >> 11;
        const int s = row & (CS - 1);
        g_biasT[(size_t)(lane * CB + b) * CS + s] = expf(Aw[lane] * sp);
    }
}

// ===========================================================================
// Kernel 4: causal flash attention, tf32 mma; all mma inputs RNA-pre-rounded
// Epilogue writes hi/lo split directly for k_out.
// ===========================================================================
#define KSTR 132
#define VSTR 136
#define PST 68
#define AT_KS 0
#define AT_VS (2 * 64 * KSTR)
#define AT_PS (AT_VS + 2 * 64 * VSTR)
#define AT_BIAS (AT_PS + 128 * PST)
#define ATTN_TC_FLOATS (AT_BIAS + 2 * 64)
#define ATTN_TC_BYTES (ATTN_TC_FLOATS * 4)

__global__ void __launch_bounds__(256, 1) k_attn_tc()
{
    extern __shared__ float sm[];
    float* Ks = sm + AT_KS;
    float* Vs = sm + AT_VS;
    float* Ps = sm + AT_PS;
    float* bias_s = sm + AT_BIAS;
    const unsigned smBase = (unsigned)__cvta_generic_to_shared(sm);

    const int tid = threadIdx.x;
    const int w = tid >> 5, lane = tid & 31;
    const int g = lane >> 2, t = lane & 3;
    const int bh = blockIdx.x;
    const int b = bh >> 3;
    const int h = bh & 7;
    const int kvh = h >> 1;
    const int qt = (int)gridDim.y - 1 - (int)blockIdx.y;
    const int q0 = qt * 128;
    const int qw = w * 16;
    const int qg0 = q0 + qw + g;
    const int qg1 = qg0 + 8;

    unsigned aq[16][4];
    {
        const float* qp = g_q + (size_t)(b * CS + qg0) * 1024 + h * 128;
#pragma unroll
        for (int kf = 0; kf < 16; ++kf) {
            aq[kf][0] = __float_as_uint(qp[kf * 8 + t]);
            aq[kf][1] = __float_as_uint(qp[8 * 1024 + kf * 8 + t]);
            aq[kf][2] = __float_as_uint(qp[kf * 8 + t + 4]);
            aq[kf][3] = __float_as_uint(qp[8 * 1024 + kf * 8 + t + 4]);
        }
    }

    float O[16][4];
#pragma unroll
    for (int nt = 0; nt < 16; ++nt)
#pragma unroll
        for (int r = 0; r < 4; ++r) O[nt][r] = 0.f;
    float m0 = -1e30f, m1 = -1e30f, l0 = 0.f, l1 = 0.f;

    const int nkt = 2 * qt + 2;

    auto issue = [&](int kt, int st) {
        const int kbase = kt * 64;
#pragma unroll
        for (int i = 0; i < 8; ++i) {
            const int idx = tid + i * 256;
            const int c = idx >> 5, dc = (idx & 31) << 2;
            const size_t grow = (size_t)(b * CS + kbase + c) * 512 + kvh * 128 + dc;
            cp16(smBase + (unsigned)((AT_KS + st * 64 * KSTR + c * KSTR + dc) << 2), g_k + grow);
            cp16(smBase + (unsigned)((AT_VS + st * 64 * VSTR + c * VSTR + dc) << 2), g_v + grow);
        }
        if (tid < 16)
            cp16(smBase + (unsigned)((AT_BIAS + st * 64 + tid * 4) << 2),
                 g_biasT + (size_t)(h * CB + b) * CS + kbase + tid * 4);
        asm volatile("cp.async.commit_group;\n");
    };

    issue(0, 0);
    int st = 0;
    for (int kt = 0; kt < nkt; ++kt) {
        const int kbase = kt * 64;
        asm volatile("cp.async.wait_group 0;\n");
        __syncthreads();
        if (kt + 1 < nkt) issue(kt + 1, st ^ 1);

        const float* KsS = Ks + st * 64 * KSTR;
        const float* VsS = Vs + st * 64 * VSTR;
        const float* biasS = bias_s + st * 64;

        float sacc[8][4];
#pragma unroll
        for (int nt = 0; nt < 8; ++nt)
#pragma unroll
            for (int r = 0; r < 4; ++r) sacc[nt][r] = 0.f;
#pragma unroll
        for (int kf = 0; kf < 16; ++kf) {
#pragma unroll
            for (int nt = 0; nt < 8; ++nt) {
                unsigned bf[2];
                const float* kp = KsS + (nt * 8 + g) * KSTR + kf * 8 + t;
                bf[0] = __float_as_uint(kp[0]);
                bf[1] = __float_as_uint(kp[4]);
                mma_tf32(sacc[nt], aq[kf], bf);
            }
        }

        float mx0 = -1e30f, mx1 = -1e30f;
#pragma unroll
        for (int nt = 0; nt < 8; ++nt) {
            const int kg = kbase + nt * 8 + 2 * t;
            const float b0 = biasS[nt * 8 + 2 * t];
            const float b1 = biasS[nt * 8 + 2 * t + 1];
            sacc[nt][0] = (kg     <= qg0) ? fmaf(sacc[nt][0], CSCALE, b0) : -1e30f;
            sacc[nt][1] = (kg + 1 <= qg0) ? fmaf(sacc[nt][1], CSCALE, b1) : -1e30f;
            sacc[nt][2] = (kg     <= qg1) ? fmaf(sacc[nt][2], CSCALE, b0) : -1e30f;
            sacc[nt][3] = (kg + 1 <= qg1) ? fmaf(sacc[nt][3], CSCALE, b1) : -1e30f;
            mx0 = fmaxf(mx0, fmaxf(sacc[nt][0], sacc[nt][1]));
            mx1 = fmaxf(mx1, fmaxf(sacc[nt][2], sacc[nt][3]));
        }
        mx0 = fmaxf(mx0, __shfl_xor_sync(0xffffffffu, mx0, 1));
        mx0 = fmaxf(mx0, __shfl_xor_sync(0xffffffffu, mx0, 2));
        mx1 = fmaxf(mx1, __shfl_xor_sync(0xffffffffu, mx1, 1));
        mx1 = fmaxf(mx1, __shfl_xor_sync(0xffffffffu, mx1, 2));

        const float mn0 = fmaxf(m0, mx0);
        const float mn1 = fmaxf(m1, mx1);
        const float alpha0 = __expf(m0 - mn0);
        const float alpha1 = __expf(m1 - mn1);
        float sum0 = 0.f, sum1 = 0.f;
#pragma unroll
        for (int nt = 0; nt < 8; ++nt) {
            const float p0 = tf32r(__expf(sacc[nt][0] - mn0));
            const float p1 = tf32r(__expf(sacc[nt][1] - mn0));
            const float p2 = tf32r(__expf(sacc[nt][2] - mn1));
            const float p3 = tf32r(__expf(sacc[nt][3] - mn1));
            sum0 += p0 + p1;
            sum1 += p2 + p3;
            *(float2*)&Ps[(qw + g) * PST + nt * 8 + 2 * t]     = make_float2(p0, p1);
            *(float2*)&Ps[(qw + g + 8) * PST + nt * 8 + 2 * t] = make_float2(p2, p3);
        }
        sum0 += __shfl_xor_sync(0xffffffffu, sum0, 1);
        sum0 += __shfl_xor_sync(0xffffffffu, sum0, 2);
        sum1 += __shfl_xor_sync(0xffffffffu, sum1, 1);
        sum1 += __shfl_xor_sync(0xffffffffu, sum1, 2);
        l0 = l0 * alpha0 + sum0;  m0 = mn0;
        l1 = l1 * alpha1 + sum1;  m1 = mn1;

#pragma unroll
        for (int nt = 0; nt < 16; ++nt) {
            O[nt][0] *= alpha0; O[nt][1] *= alpha0;
            O[nt][2] *= alpha1; O[nt][3] *= alpha1;
        }

        __syncwarp();
#pragma unroll
        for (int kf = 0; kf < 8; ++kf) {
            unsigned ap[4];
            const float* pp = Ps + (qw + g) * PST + kf * 8 + t;
            ap[0] = __float_as_uint(pp[0]);
            ap[1] = __float_as_uint(pp[8 * PST]);
            ap[2] = __float_as_uint(pp[4]);
            ap[3] = __float_as_uint(pp[8 * PST + 4]);
#pragma unroll
            for (int nt = 0; nt < 16; ++nt) {
                unsigned bf[2];
                const float* vp = VsS + (kf * 8 + t) * VSTR + nt * 8 + g;
                bf[0] = __float_as_uint(vp[0]);
                bf[1] = __float_as_uint(vp[4 * VSTR]);
                mma_tf32(O[nt], ap, bf);
            }
        }
        __syncthreads();
        st ^= 1;
    }

    // epilogue: normalize; write tf32 hi/lo split for the output GEMM
    const float inv0 = 1.f / l0;
    const float inv1 = 1.f / l1;
    const size_t r0 = (size_t)(b * CS + qg0) * 1024 + h * 128;
    const size_t r1 = (size_t)(b * CS + qg1) * 1024 + h * 128;
#pragma unroll
    for (int nt = 0; nt < 16; ++nt) {
        const float o0 = O[nt][0] * inv0, o1 = O[nt][1] * inv0;
        const float o2 = O[nt][2] * inv1, o3 = O[nt][3] * inv1;
        const float h0 = tf32r(o0), h1 = tf32r(o1), h2 = tf32r(o2), h3 = tf32r(o3);
        *(float2*)(g_at_hi + r0 + nt * 8 + 2 * t) = make_float2(h0, h1);
        *(float2*)(g_at_lo + r0 + nt * 8 + 2 * t) = make_float2(tf32r(o0 - h0), tf32r(o1 - h1));
        *(float2*)(g_at_hi + r1 + nt * 8 + 2 * t) = make_float2(h2, h3);
        *(float2*)(g_at_lo + r1 + nt * 8 + 2 * t) = make_float2(tf32r(o2 - h2), tf32r(o3 - h3));
    }
}

// ---------------------------------------------------------------------------
extern "C" void kernel_launch(void* const* d_in, const int* in_sizes, int n_in,
                              void* d_out, int out_size)
{
    const float* hidden = (const float*)d_in[0];
    const float* Wq     = (const float*)d_in[1];
    const float* Wk     = (const float*)d_in[2];
    const float* Wv     = (const float*)d_in[3];
    const float* Wdt    = (const float*)d_in[4];
    const float* Aw     = (const float*)d_in[5];
    const float* Wo     = (const float*)d_in[6];
    const float* cosb   = (const float*)d_in[7];
    const float* sinb   = (const float*)d_in[8];
    float* out = (float*)d_out;

    cudaFuncSetAttribute(k_qkv_tc,  cudaFuncAttributeMaxDynamicSharedMemorySize, GEMM_SMEM_BYTES);
    cudaFuncSetAttribute(k_out_tc,  cudaFuncAttributeMaxDynamicSharedMemorySize, GEMM_SMEM_BYTES);
    cudaFuncSetAttribute(k_attn_tc, cudaFuncAttributeMaxDynamicSharedMemorySize, ATTN_TC_BYTES);

    // one-time splits; destinations chosen by tag INSIDE the kernel
    k_cvt4<<<(CBS * CHID / 4 + 255) / 256, 256>>>(hidden, 0, CBS * CHID / 4);
    k_cvt4<<<(CHID * 1024 / 4 + 255) / 256, 256>>>(Wq, 1, CHID * 1024 / 4);
    k_cvt4<<<(CHID * 512 / 4 + 255) / 256, 256>>>(Wk, 2, CHID * 512 / 4);
    k_cvt4<<<(CHID * 512 / 4 + 255) / 256, 256>>>(Wv, 3, CHID * 512 / 4);
    k_cvt4<<<(1024 * CHID / 4 + 255) / 256, 256>>>(Wo, 4, 1024 * CHID / 4);

    k_qkv_tc<<<dim3(16, 32), 256, GEMM_SMEM_BYTES>>>();
    k_rope<<<(CBS * 12 * 64 + 255) / 256, 256>>>(cosb, sinb);
    k_biask<<<CBS / 8, 256>>>(Wdt, Aw);
    k_attn_tc<<<dim3(16, 16), 256, ATTN_TC_BYTES>>>();
    k_out_tc<<<dim3(8, 32), 256, GEMM_SMEM_BYTES>>>(out);
}

// round 10
// speedup vs baseline: 2.5488x; 1.4812x over previous
#include <cuda_runtime.h>
#include <cuda_bf16.h>
#include <math.h>

// Problem constants
#define CB 2
#define CS 2048
#define CHID 1024
#define CH 8
#define CKV 4
#define CD 128
#define CBS (CB * CS)                 // 4096 rows
#define CSCALE 0.08838834764831845f   // 128^-0.5

// Scratch (allocation-free rule: __device__ globals)
__device__ float g_q[CBS * CH * CD];      // rope'd, tf32-RNA rounded
__device__ float g_k[CBS * CKV * CD];     // rope'd, tf32-RNA rounded
__device__ float g_v[CBS * CKV * CD];     // tf32-RNA rounded at qkv epilogue
__device__ float g_biasT[CH * CB * CS];   // dyn transposed: [h][b][s]

// bf16x3 packed operands: u32 = bf16 pair along K; hi and lo arrays.
__device__ unsigned g_hid_hi[CBS * 512], g_hid_lo[CBS * 512];   // [row][k2]
__device__ unsigned g_wq_hi[1024 * 512], g_wq_lo[1024 * 512];   // [col][k2]
__device__ unsigned g_wk_hi[512 * 512],  g_wk_lo[512 * 512];
__device__ unsigned g_wv_hi[512 * 512],  g_wv_lo[512 * 512];
__device__ unsigned g_wo_hi[1024 * 512], g_wo_lo[1024 * 512];
__device__ unsigned g_at_hi[CBS * 512],  g_at_lo[CBS * 512];    // attn out packed

__device__ __forceinline__ void cp16(unsigned dst, const void* src) {
    asm volatile("cp.async.cg.shared.global [%0], [%1], 16;\n" :: "r"(dst), "l"(src));
}

__device__ __forceinline__ unsigned f2tf32(float x) {
    unsigned r;
    asm("cvt.rna.tf32.f32 %0, %1;\n" : "=r"(r) : "f"(x));
    return r;
}
__device__ __forceinline__ float tf32r(float x) { return __uint_as_float(f2tf32(x)); }

__device__ __forceinline__ void mma_tf32(float* d, const unsigned* a, const unsigned* b) {
    asm volatile(
        "mma.sync.aligned.m16n8k8.row.col.f32.tf32.tf32.f32 "
        "{%0,%1,%2,%3}, {%4,%5,%6,%7}, {%8,%9}, {%0,%1,%2,%3};\n"
        : "+f"(d[0]), "+f"(d[1]), "+f"(d[2]), "+f"(d[3])
        : "r"(a[0]), "r"(a[1]), "r"(a[2]), "r"(a[3]), "r"(b[0]), "r"(b[1]));
}

__device__ __forceinline__ void mma_bf16(float* d, const unsigned* a, const unsigned* b) {
    asm volatile(
        "mma.sync.aligned.m16n8k16.row.col.f32.bf16.bf16.f32 "
        "{%0,%1,%2,%3}, {%4,%5,%6,%7}, {%8,%9}, {%0,%1,%2,%3};\n"
        : "+f"(d[0]), "+f"(d[1]), "+f"(d[2]), "+f"(d[3])
        : "r"(a[0]), "r"(a[1]), "r"(a[2]), "r"(a[3]), "r"(b[0]), "r"(b[1]));
}

// pack pair (x0 -> low16, x1 -> high16) into hi/lo bf16 residual split
__device__ __forceinline__ void bf16x3_pack(float x0, float x1, unsigned& hi, unsigned& lo) {
    const __nv_bfloat16 h0 = __float2bfloat16_rn(x0);
    const __nv_bfloat16 h1 = __float2bfloat16_rn(x1);
    const __nv_bfloat16 l0 = __float2bfloat16_rn(x0 - __bfloat162float(h0));
    const __nv_bfloat16 l1 = __float2bfloat16_rn(x1 - __bfloat162float(h1));
    __nv_bfloat162 H; H.x = h0; H.y = h1;
    __nv_bfloat162 L; L.x = l0; L.y = l1;
    hi = *(const unsigned*)&H;
    lo = *(const unsigned*)&L;
}

// ---------------------------------------------------------------------------
// Convert kernels. DESTINATIONS RESOLVED IN DEVICE CODE ONLY (tag dispatch) —
// __device__ symbols passed as host-side kernel args resolve to the host
// shadow, silently ATS-written on GB300 (the round-6/8 zero-output bug).
// ---------------------------------------------------------------------------
__global__ void k_cvtA(const float* __restrict__ hidden)
{
    const int idx = blockIdx.x * blockDim.x + threadIdx.x;   // over CBS*512
    if (idx >= CBS * 512) return;
    const float2 v = *(const float2*)(hidden + (size_t)idx * 2);
    bf16x3_pack(v.x, v.y, g_hid_hi[idx], g_hid_lo[idx]);
}

// src: [1024, N] row-major -> dst [N][512] packed pairs along K (transposed)
__global__ void __launch_bounds__(256) k_cvtW(
    const float* __restrict__ src, int which, int N)
{
    unsigned* dhi; unsigned* dlo;
    switch (which) {
        case 1:  dhi = g_wq_hi; dlo = g_wq_lo; break;
        case 2:  dhi = g_wk_hi; dlo = g_wk_lo; break;
        case 3:  dhi = g_wv_hi; dlo = g_wv_lo; break;
        default: dhi = g_wo_hi; dlo = g_wo_lo; break;
    }
    __shared__ float smW[64][33];
    const int tid = threadIdx.x;
    const int k0 = blockIdx.x * 64;
    const int n0 = blockIdx.y * 32;
#pragma unroll
    for (int i = 0; i < 8; ++i) {
        const int idx = tid + i * 256;
        const int r = idx >> 5, c = idx & 31;
        smW[r][c] = src[(size_t)(k0 + r) * N + n0 + c];
    }
    __syncthreads();
    const int n = tid >> 3;
#pragma unroll
    for (int j = 0; j < 4; ++j) {
        const int k2 = (tid & 7) + j * 8;        // 0..31 local
        unsigned hi, lo;
        bf16x3_pack(smW[2 * k2][n], smW[2 * k2 + 1][n], hi, lo);
        const size_t o = (size_t)(n0 + n) * 512 + (k0 >> 1) + k2;
        dhi[o] = hi; dlo[o] = lo;
    }
}

// ===========================================================================
// bf16x3 tensor-core GEMM: C[128,128] = A[128,1024] @ B[1024,128]
// A,B pre-packed (hi/lo u32 pairs). 8 warps (2Mx4N), warp 64x32, m16n8k16.
// smem stride 20 u32 (banks 20g+t bijective -> conflict-free).
// ===========================================================================
#define PSTRIDE 20
#define STG_U32 (128 * PSTRIDE)       // 2560 per array per stage
#define SA_H 0
#define SA_L (2 * STG_U32)            // 5120
#define SB_H (4 * STG_U32)            // 10240
#define SB_L (6 * STG_U32)            // 15360
#define GEMM_SMEM_BYTES (8 * STG_U32 * 4)   // 81920

__device__ __forceinline__ void gemm128_bf16x3(
    const unsigned* __restrict__ Ahi, const unsigned* __restrict__ Alo, int arow0,
    const unsigned* __restrict__ Bhi, const unsigned* __restrict__ Blo, int bcol0,
    float* __restrict__ C, int ldc, bool roundC)
{
    extern __shared__ unsigned smu[];
    const unsigned smBase = (unsigned)__cvta_generic_to_shared(smu);

    const int tid = threadIdx.x;
    const int w = tid >> 5, lane = tid & 31;
    const int g = lane >> 2, t = lane & 3;
    const int rb = (w >> 2) * 64;   // warp row base (2 warps in M)
    const int cb = (w & 3) * 32;    // warp col base (4 warps in N)

    float acc[4][4][4];
#pragma unroll
    for (int mt = 0; mt < 4; ++mt)
#pragma unroll
        for (int nt = 0; nt < 4; ++nt)
#pragma unroll
            for (int r = 0; r < 4; ++r) acc[mt][nt][r] = 0.f;

    const unsigned* srcs[4] = { Ahi, Alo, Bhi, Blo };
    const int base0[4] = { arow0, arow0, bcol0, bcol0 };
    const int dstb[4] = { SA_H, SA_L, SB_H, SB_L };

    auto issue = [&](int k0, int st) {
        const int k2_0 = k0 >> 1;
#pragma unroll
        for (int i = 0; i < 8; ++i) {
            const int idx = tid + i * 256;            // 0..2047
            const int sub = idx >> 9;                 // array 0..3
            const int j = idx & 511;
            const int r = j >> 2, c4 = (j & 3) << 2;  // 16 u32 per row
            cp16(smBase + (unsigned)((dstb[sub] + st * STG_U32 + r * PSTRIDE + c4) << 2),
                 srcs[sub] + (size_t)(base0[sub] + r) * 512 + k2_0 + c4);
        }
        asm volatile("cp.async.commit_group;\n");
    };

    issue(0, 0);
    int st = 0;
    for (int k0 = 0; k0 < 1024; k0 += 32) {
        asm volatile("cp.async.wait_group 0;\n");
        __syncthreads();
        if (k0 + 32 < 1024) issue(k0 + 32, st ^ 1);
        const unsigned* AH = smu + SA_H + st * STG_U32;
        const unsigned* AL = smu + SA_L + st * STG_U32;
        const unsigned* BH = smu + SB_H + st * STG_U32;
        const unsigned* BL = smu + SB_L + st * STG_U32;
#pragma unroll
        for (int ks = 0; ks < 2; ++ks) {
            const int kk2 = ks * 8;
            unsigned ah[4][4], al[4][4], bh[4][2], bl[4][2];
#pragma unroll
            for (int mt = 0; mt < 4; ++mt) {
                const int ro = (rb + mt * 16 + g) * PSTRIDE + kk2;
                ah[mt][0] = AH[ro + t];
                ah[mt][1] = AH[ro + 8 * PSTRIDE + t];
                ah[mt][2] = AH[ro + t + 4];
                ah[mt][3] = AH[ro + 8 * PSTRIDE + t + 4];
                al[mt][0] = AL[ro + t];
                al[mt][1] = AL[ro + 8 * PSTRIDE + t];
                al[mt][2] = AL[ro + t + 4];
                al[mt][3] = AL[ro + 8 * PSTRIDE + t + 4];
            }
#pragma unroll
            for (int nt = 0; nt < 4; ++nt) {
                const int co = (cb + nt * 8 + g) * PSTRIDE + kk2;
                bh[nt][0] = BH[co + t];
                bh[nt][1] = BH[co + t + 4];
                bl[nt][0] = BL[co + t];
                bl[nt][1] = BL[co + t + 4];
            }
#pragma unroll
            for (int mt = 0; mt < 4; ++mt)
#pragma unroll
                for (int nt = 0; nt < 4; ++nt) {
                    mma_bf16(acc[mt][nt], al[mt], bh[nt]);   // lo*hi
                    mma_bf16(acc[mt][nt], ah[mt], bl[nt]);   // hi*lo
                    mma_bf16(acc[mt][nt], ah[mt], bh[nt]);   // hi*hi
                }
        }
        st ^= 1;
    }

#pragma unroll
    for (int mt = 0; mt < 4; ++mt)
#pragma unroll
        for (int nt = 0; nt < 4; ++nt) {
            const int r0 = rb + mt * 16 + g;
            const int c0 = cb + nt * 8 + 2 * t;
            float v0 = acc[mt][nt][0], v1 = acc[mt][nt][1];
            float v2 = acc[mt][nt][2], v3 = acc[mt][nt][3];
            if (roundC) { v0 = tf32r(v0); v1 = tf32r(v1); v2 = tf32r(v2); v3 = tf32r(v3); }
            *(float2*)(C + (size_t)r0 * ldc + c0)       = make_float2(v0, v1);
            *(float2*)(C + (size_t)(r0 + 8) * ldc + c0) = make_float2(v2, v3);
        }
}

// Kernel 1: fused QKV projection; V output rounded to tf32 (PV exactness)
__global__ void __launch_bounds__(256) k_qkv_tc()
{
    const int n0 = blockIdx.x * 128;
    const int m0 = blockIdx.y * 128;
    if (n0 < 1024)
        gemm128_bf16x3(g_hid_hi, g_hid_lo, m0, g_wq_hi, g_wq_lo, n0,
                       g_q + (size_t)m0 * 1024 + n0, 1024, false);
    else if (n0 < 1536)
        gemm128_bf16x3(g_hid_hi, g_hid_lo, m0, g_wk_hi, g_wk_lo, n0 - 1024,
                       g_k + (size_t)m0 * 512 + (n0 - 1024), 512, false);
    else
        gemm128_bf16x3(g_hid_hi, g_hid_lo, m0, g_wv_hi, g_wv_lo, n0 - 1536,
                       g_v + (size_t)m0 * 512 + (n0 - 1536), 512, true);
}

// Kernel 5: output projection from packed attention output
__global__ void __launch_bounds__(256) k_out_tc(float* __restrict__ out)
{
    const int n0 = blockIdx.x * 128;
    const int m0 = blockIdx.y * 128;
    gemm128_bf16x3(g_at_hi, g_at_lo, m0, g_wo_hi, g_wo_lo, n0,
                   out + (size_t)m0 * 1024 + n0, 1024, false);
}

// ---------------------------------------------------------------------------
// Kernel 2: RoPE on q and k -- writes tf32-RNA-rounded values (QK exactness)
// ---------------------------------------------------------------------------
__global__ void k_rope(const float* __restrict__ cosb, const float* __restrict__ sinb)
{
    const int t = blockIdx.x * blockDim.x + threadIdx.x;
    const int total = CBS * 12 * 64;
    if (t >= total) return;
    const int d = t & 63;
    const int head = (t >> 6) % 12;
    const int row = t / (12 * 64);
    const int s = row & (CS - 1);
    const float c1  = cosb[s * CD + d];
    const float sn1 = sinb[s * CD + d];
    const float c2  = cosb[s * CD + d + 64];
    const float sn2 = sinb[s * CD + d + 64];
    float* p;
    if (head < CH) p = g_q + (size_t)row * (CH * CD) + head * CD;
    else           p = g_k + (size_t)row * (CKV * CD) + (head - CH) * CD;
    const float x1 = p[d], x2 = p[d + 64];
    p[d]      = tf32r(x1 * c1 - x2 * sn1);
    p[d + 64] = tf32r(x2 * c2 + x1 * sn2);
}

// ---------------------------------------------------------------------------
// Kernel 3: dt = v_flat @ Wdt ; dyn = exp(A * softplus(dt)) -> g_biasT [h][b][s]
// ---------------------------------------------------------------------------
__global__ void __launch_bounds__(256) k_biask(
    const float* __restrict__ Wdt, const float* __restrict__ Aw)
{
    __shared__ float sW[512 * 8];
    for (int i = threadIdx.x; i < 512 * 8; i += 256) sW[i] = Wdt[i];
    __syncthreads();
    const int warp = threadIdx.x >> 5;
    const int lane = threadIdx.x & 31;
    const int row = blockIdx.x * 8 + warp;
    const float* vrow = g_v + (size_t)row * 512;
    float acc[8];
#pragma unroll
    for (int h = 0; h < 8; ++h) acc[h] = 0.f;
    for (int j = lane; j < 512; j += 32) {
        const float vv = vrow[j];
#pragma unroll
        for (int h = 0; h < 8; ++h) acc[h] = fmaf(vv, sW[j * 8 + h], acc[h]);
    }
#pragma unroll
    for (int off = 16; off > 0; off >>= 1)
#pragma unroll
        for (int h = 0; h < 8; ++h)
            acc[h] += __shfl_xor_sync(0xffffffffu, acc[h], off);
    if (lane < 8) {
        const float dt = acc[lane];
        const float sp = (dt > 20.f) ? dt : log1pf(expf(dt));
        const int b = row >> 11;
        const int s = row & (CS - 1);
        g_biasT[(size_t)(lane * CB + b) * CS + s] = expf(Aw[lane] * sp);
    }
}

// ===========================================================================
// Kernel 4: causal flash attention, tf32 mma; all mma inputs RNA-pre-rounded.
// Epilogue packs O into bf16 hi/lo pairs for the output GEMM.
// ===========================================================================
#define KSTR 132
#define VSTR 136
#define PST 68
#define AT_KS 0
#define AT_VS (2 * 64 * KSTR)
#define AT_PS (AT_VS + 2 * 64 * VSTR)
#define AT_BIAS (AT_PS + 128 * PST)
#define ATTN_TC_FLOATS (AT_BIAS + 2 * 64)
#define ATTN_TC_BYTES (ATTN_TC_FLOATS * 4)

__global__ void __launch_bounds__(256, 1) k_attn_tc()
{
    extern __shared__ float sm[];
    float* Ks = sm + AT_KS;
    float* Vs = sm + AT_VS;
    float* Ps = sm + AT_PS;
    float* bias_s = sm + AT_BIAS;
    const unsigned smBase = (unsigned)__cvta_generic_to_shared(sm);

    const int tid = threadIdx.x;
    const int w = tid >> 5, lane = tid & 31;
    const int g = lane >> 2, t = lane & 3;
    const int bh = blockIdx.x;
    const int b = bh >> 3;
    const int h = bh & 7;
    const int kvh = h >> 1;
    const int qt = (int)gridDim.y - 1 - (int)blockIdx.y;
    const int q0 = qt * 128;
    const int qw = w * 16;
    const int qg0 = q0 + qw + g;
    const int qg1 = qg0 + 8;

    unsigned aq[16][4];
    {
        const float* qp = g_q + (size_t)(b * CS + qg0) * 1024 + h * 128;
#pragma unroll
        for (int kf = 0; kf < 16; ++kf) {
            aq[kf][0] = __float_as_uint(qp[kf * 8 + t]);
            aq[kf][1] = __float_as_uint(qp[8 * 1024 + kf * 8 + t]);
            aq[kf][2] = __float_as_uint(qp[kf * 8 + t + 4]);
            aq[kf][3] = __float_as_uint(qp[8 * 1024 + kf * 8 + t + 4]);
        }
    }

    float O[16][4];
#pragma unroll
    for (int nt = 0; nt < 16; ++nt)
#pragma unroll
        for (int r = 0; r < 4; ++r) O[nt][r] = 0.f;
    float m0 = -1e30f, m1 = -1e30f, l0 = 0.f, l1 = 0.f;

    const int nkt = 2 * qt + 2;

    auto issue = [&](int kt, int st) {
        const int kbase = kt * 64;
#pragma unroll
        for (int i = 0; i < 8; ++i) {
            const int idx = tid + i * 256;
            const int c = idx >> 5, dc = (idx & 31) << 2;
            const size_t grow = (size_t)(b * CS + kbase + c) * 512 + kvh * 128 + dc;
            cp16(smBase + (unsigned)((AT_KS + st * 64 * KSTR + c * KSTR + dc) << 2), g_k + grow);
            cp16(smBase + (unsigned)((AT_VS + st * 64 * VSTR + c * VSTR + dc) << 2), g_v + grow);
        }
        if (tid < 16)
            cp16(smBase + (unsigned)((AT_BIAS + st * 64 + tid * 4) << 2),
                 g_biasT + (size_t)(h * CB + b) * CS + kbase + tid * 4);
        asm volatile("cp.async.commit_group;\n");
    };

    issue(0, 0);
    int st = 0;
    for (int kt = 0; kt < nkt; ++kt) {
        const int kbase = kt * 64;
        asm volatile("cp.async.wait_group 0;\n");
        __syncthreads();
        if (kt + 1 < nkt) issue(kt + 1, st ^ 1);

        const float* KsS = Ks + st * 64 * KSTR;
        const float* VsS = Vs + st * 64 * VSTR;
        const float* biasS = bias_s + st * 64;

        float sacc[8][4];
#pragma unroll
        for (int nt = 0; nt < 8; ++nt)
#pragma unroll
            for (int r = 0; r < 4; ++r) sacc[nt][r] = 0.f;
#pragma unroll
        for (int kf = 0; kf < 16; ++kf) {
#pragma unroll
            for (int nt = 0; nt < 8; ++nt) {
                unsigned bf[2];
                const float* kp = KsS + (nt * 8 + g) * KSTR + kf * 8 + t;
                bf[0] = __float_as_uint(kp[0]);
                bf[1] = __float_as_uint(kp[4]);
                mma_tf32(sacc[nt], aq[kf], bf);
            }
        }

        float mx0 = -1e30f, mx1 = -1e30f;
#pragma unroll
        for (int nt = 0; nt < 8; ++nt) {
            const int kg = kbase + nt * 8 + 2 * t;
            const float b0 = biasS[nt * 8 + 2 * t];
            const float b1 = biasS[nt * 8 + 2 * t + 1];
            sacc[nt][0] = (kg     <= qg0) ? fmaf(sacc[nt][0], CSCALE, b0) : -1e30f;
            sacc[nt][1] = (kg + 1 <= qg0) ? fmaf(sacc[nt][1], CSCALE, b1) : -1e30f;
            sacc[nt][2] = (kg     <= qg1) ? fmaf(sacc[nt][2], CSCALE, b0) : -1e30f;
            sacc[nt][3] = (kg + 1 <= qg1) ? fmaf(sacc[nt][3], CSCALE, b1) : -1e30f;
            mx0 = fmaxf(mx0, fmaxf(sacc[nt][0], sacc[nt][1]));
            mx1 = fmaxf(mx1, fmaxf(sacc[nt][2], sacc[nt][3]));
        }
        mx0 = fmaxf(mx0, __shfl_xor_sync(0xffffffffu, mx0, 1));
        mx0 = fmaxf(mx0, __shfl_xor_sync(0xffffffffu, mx0, 2));
        mx1 = fmaxf(mx1, __shfl_xor_sync(0xffffffffu, mx1, 1));
        mx1 = fmaxf(mx1, __shfl_xor_sync(0xffffffffu, mx1, 2));

        const float mn0 = fmaxf(m0, mx0);
        const float mn1 = fmaxf(m1, mx1);
        const float alpha0 = __expf(m0 - mn0);
        const float alpha1 = __expf(m1 - mn1);
        float sum0 = 0.f, sum1 = 0.f;
#pragma unroll
        for (int nt = 0; nt < 8; ++nt) {
            const float p0 = tf32r(__expf(sacc[nt][0] - mn0));
            const float p1 = tf32r(__expf(sacc[nt][1] - mn0));
            const float p2 = tf32r(__expf(sacc[nt][2] - mn1));
            const float p3 = tf32r(__expf(sacc[nt][3] - mn1));
            sum0 += p0 + p1;
            sum1 += p2 + p3;
            *(float2*)&Ps[(qw + g) * PST + nt * 8 + 2 * t]     = make_float2(p0, p1);
            *(float2*)&Ps[(qw + g + 8) * PST + nt * 8 + 2 * t] = make_float2(p2, p3);
        }
        sum0 += __shfl_xor_sync(0xffffffffu, sum0, 1);
        sum0 += __shfl_xor_sync(0xffffffffu, sum0, 2);
        sum1 += __shfl_xor_sync(0xffffffffu, sum1, 1);
        sum1 += __shfl_xor_sync(0xffffffffu, sum1, 2);
        l0 = l0 * alpha0 + sum0;  m0 = mn0;
        l1 = l1 * alpha1 + sum1;  m1 = mn1;

#pragma unroll
        for (int nt = 0; nt < 16; ++nt) {
            O[nt][0] *= alpha0; O[nt][1] *= alpha0;
            O[nt][2] *= alpha1; O[nt][3] *= alpha1;
        }

        __syncwarp();
#pragma unroll
        for (int kf = 0; kf < 8; ++kf) {
            unsigned ap[4];
            const float* pp = Ps + (qw + g) * PST + kf * 8 + t;
            ap[0] = __float_as_uint(pp[0]);
            ap[1] = __float_as_uint(pp[8 * PST]);
            ap[2] = __float_as_uint(pp[4]);
            ap[3] = __float_as_uint(pp[8 * PST + 4]);
#pragma unroll
            for (int nt = 0; nt < 16; ++nt) {
                unsigned bf[2];
                const float* vp = VsS + (kf * 8 + t) * VSTR + nt * 8 + g;
                bf[0] = __float_as_uint(vp[0]);
                bf[1] = __float_as_uint(vp[4 * VSTR]);
                mma_tf32(O[nt], ap, bf);
            }
        }
        __syncthreads();
        st ^= 1;
    }

    // epilogue: normalize and pack to bf16x3 operand layout for k_out.
    // O[nt][0],O[nt][1] are adjacent channels (2t, 2t+1) -> one packed u32.
    const float inv0 = 1.f / l0;
    const float inv1 = 1.f / l1;
    const size_t r0 = (size_t)(b * CS + qg0) * 512 + h * 64;
    const size_t r1 = (size_t)(b * CS + qg1) * 512 + h * 64;
#pragma unroll
    for (int nt = 0; nt < 16; ++nt) {
        unsigned hi, lo;
        bf16x3_pack(O[nt][0] * inv0, O[nt][1] * inv0, hi, lo);
        g_at_hi[r0 + nt * 4 + t] = hi;
        g_at_lo[r0 + nt * 4 + t] = lo;
        bf16x3_pack(O[nt][2] * inv1, O[nt][3] * inv1, hi, lo);
        g_at_hi[r1 + nt * 4 + t] = hi;
        g_at_lo[r1 + nt * 4 + t] = lo;
    }
}

// ---------------------------------------------------------------------------
extern "C" void kernel_launch(void* const* d_in, const int* in_sizes, int n_in,
                              void* d_out, int out_size)
{
    const float* hidden = (const float*)d_in[0];
    const float* Wq     = (const float*)d_in[1];
    const float* Wk     = (const float*)d_in[2];
    const float* Wv     = (const float*)d_in[3];
    const float* Wdt    = (const float*)d_in[4];
    const float* Aw     = (const float*)d_in[5];
    const float* Wo     = (const float*)d_in[6];
    const float* cosb   = (const float*)d_in[7];
    const float* sinb   = (const float*)d_in[8];
    float* out = (float*)d_out;

    cudaFuncSetAttribute(k_qkv_tc,  cudaFuncAttributeMaxDynamicSharedMemorySize, GEMM_SMEM_BYTES);
    cudaFuncSetAttribute(k_out_tc,  cudaFuncAttributeMaxDynamicSharedMemorySize, GEMM_SMEM_BYTES);
    cudaFuncSetAttribute(k_attn_tc, cudaFuncAttributeMaxDynamicSharedMemorySize, ATTN_TC_BYTES);

    // one-time packs; destinations resolved inside device code
    k_cvtA<<<(CBS * 512 + 255) / 256, 256>>>(hidden);
    k_cvtW<<<dim3(16, 32), 256>>>(Wq, 1, 1024);
    k_cvtW<<<dim3(16, 16), 256>>>(Wk, 2, 512);
    k_cvtW<<<dim3(16, 16), 256>>>(Wv, 3, 512);
    k_cvtW<<<dim3(16, 32), 256>>>(Wo, 4, 1024);

    k_qkv_tc<<<dim3(16, 32), 256, GEMM_SMEM_BYTES>>>();
    k_rope<<<(CBS * 12 * 64 + 255) / 256, 256>>>(cosb, sinb);
    k_biask<<<CBS / 8, 256>>>(Wdt, Aw);
    k_attn_tc<<<dim3(16, 16), 256, ATTN_TC_BYTES>>>();
    k_out_tc<<<dim3(8, 32), 256, GEMM_SMEM_BYTES>>>(out);
}

// round 12
// speedup vs baseline: 2.6246x; 1.0297x over previous
#include <cuda_runtime.h>
#include <cuda_bf16.h>
#include <math.h>

// Problem constants
#define CB 2
#define CS 2048
#define CHID 1024
#define CH 8
#define CKV 4
#define CD 128
#define CBS (CB * CS)                 // 4096 rows
#define CSCALE 0.08838834764831845f   // 128^-0.5

// Scratch (allocation-free rule: __device__ globals)
__device__ float g_q[CBS * CH * CD];      // rope'd, tf32-RNA rounded
__device__ float g_k[CBS * CKV * CD];     // rope'd, tf32-RNA rounded
__device__ float g_v[CBS * CKV * CD];     // tf32-RNA rounded at qkv epilogue
__device__ float g_biasT[CH * CB * CS];   // dyn transposed: [h][b][s]

// bf16x3 packed operands: u32 = bf16 pair along K; hi and lo arrays.
__device__ unsigned g_hid_hi[CBS * 512], g_hid_lo[CBS * 512];   // [row][k2]
__device__ unsigned g_wq_hi[1024 * 512], g_wq_lo[1024 * 512];   // [col][k2]
__device__ unsigned g_wk_hi[512 * 512],  g_wk_lo[512 * 512];
__device__ unsigned g_wv_hi[512 * 512],  g_wv_lo[512 * 512];
__device__ unsigned g_wo_hi[1024 * 512], g_wo_lo[1024 * 512];
__device__ unsigned g_at_hi[CBS * 512],  g_at_lo[CBS * 512];    // attn out packed

__device__ __forceinline__ void cp16(unsigned dst, const void* src) {
    asm volatile("cp.async.cg.shared.global [%0], [%1], 16;\n" :: "r"(dst), "l"(src));
}

__device__ __forceinline__ unsigned f2tf32(float x) {
    unsigned r;
    asm("cvt.rna.tf32.f32 %0, %1;\n" : "=r"(r) : "f"(x));
    return r;
}
__device__ __forceinline__ float tf32r(float x) { return __uint_as_float(f2tf32(x)); }

__device__ __forceinline__ void mma_tf32(float* d, const unsigned* a, const unsigned* b) {
    asm volatile(
        "mma.sync.aligned.m16n8k8.row.col.f32.tf32.tf32.f32 "
        "{%0,%1,%2,%3}, {%4,%5,%6,%7}, {%8,%9}, {%0,%1,%2,%3};\n"
        : "+f"(d[0]), "+f"(d[1]), "+f"(d[2]), "+f"(d[3])
        : "r"(a[0]), "r"(a[1]), "r"(a[2]), "r"(a[3]), "r"(b[0]), "r"(b[1]));
}

__device__ __forceinline__ void mma_bf16(float* d, const unsigned* a, const unsigned* b) {
    asm volatile(
        "mma.sync.aligned.m16n8k16.row.col.f32.bf16.bf16.f32 "
        "{%0,%1,%2,%3}, {%4,%5,%6,%7}, {%8,%9}, {%0,%1,%2,%3};\n"
        : "+f"(d[0]), "+f"(d[1]), "+f"(d[2]), "+f"(d[3])
        : "r"(a[0]), "r"(a[1]), "r"(a[2]), "r"(a[3]), "r"(b[0]), "r"(b[1]));
}

// pack pair (x0 -> low16, x1 -> high16) into hi/lo bf16 residual split
__device__ __forceinline__ void bf16x3_pack(float x0, float x1, unsigned& hi, unsigned& lo) {
    const __nv_bfloat16 h0 = __float2bfloat16_rn(x0);
    const __nv_bfloat16 h1 = __float2bfloat16_rn(x1);
    const __nv_bfloat16 l0 = __float2bfloat16_rn(x0 - __bfloat162float(h0));
    const __nv_bfloat16 l1 = __float2bfloat16_rn(x1 - __bfloat162float(h1));
    __nv_bfloat162 H; H.x = h0; H.y = h1;
    __nv_bfloat162 L; L.x = l0; L.y = l1;
    hi = *(const unsigned*)&H;
    lo = *(const unsigned*)&L;
}

// ---------------------------------------------------------------------------
// Convert kernels (destinations resolved in device code only — GB300 ATS trap:
// __device__ symbols passed as host-side kernel args resolve to host shadows)
// ---------------------------------------------------------------------------
__global__ void k_cvtA(const float* __restrict__ hidden)
{
    const int idx = blockIdx.x * blockDim.x + threadIdx.x;   // over CBS*512
    if (idx >= CBS * 512) return;
    const float2 v = *(const float2*)(hidden + (size_t)idx * 2);
    bf16x3_pack(v.x, v.y, g_hid_hi[idx], g_hid_lo[idx]);
}

__global__ void __launch_bounds__(256) k_cvtW(
    const float* __restrict__ src, int which, int N)
{
    unsigned* dhi; unsigned* dlo;
    switch (which) {
        case 1:  dhi = g_wq_hi; dlo = g_wq_lo; break;
        case 2:  dhi = g_wk_hi; dlo = g_wk_lo; break;
        case 3:  dhi = g_wv_hi; dlo = g_wv_lo; break;
        default: dhi = g_wo_hi; dlo = g_wo_lo; break;
    }
    __shared__ float smW[64][33];
    const int tid = threadIdx.x;
    const int k0 = blockIdx.x * 64;
    const int n0 = blockIdx.y * 32;
#pragma unroll
    for (int i = 0; i < 8; ++i) {
        const int idx = tid + i * 256;
        const int r = idx >> 5, c = idx & 31;
        smW[r][c] = src[(size_t)(k0 + r) * N + n0 + c];
    }
    __syncthreads();
    const int n = tid >> 3;
#pragma unroll
    for (int j = 0; j < 4; ++j) {
        const int k2 = (tid & 7) + j * 8;
        unsigned hi, lo;
        bf16x3_pack(smW[2 * k2][n], smW[2 * k2 + 1][n], hi, lo);
        const size_t o = (size_t)(n0 + n) * 512 + (k0 >> 1) + k2;
        dhi[o] = hi; dlo[o] = lo;
    }
}

// ===========================================================================
// bf16x3 tensor-core GEMM: C[128,128] = A[128,1024] @ B[1024,128]
// A,B pre-packed (hi/lo u32 pairs). 8 warps (2Mx4N), warp 64x32, m16n8k16.
// smem stride 20 u32 (banks 20g+t bijective -> conflict-free).
// 80KB smem/CTA -> __launch_bounds__(256, 2): two CTAs per SM fill the
// per-chunk wait/barrier bubbles with each other's HMMA work.
// ===========================================================================
#define PSTRIDE 20
#define STG_U32 (128 * PSTRIDE)       // 2560 per array per stage
#define SA_H 0
#define SA_L (2 * STG_U32)            // 5120
#define SB_H (4 * STG_U32)            // 10240
#define SB_L (6 * STG_U32)            // 15360
#define GEMM_SMEM_BYTES (8 * STG_U32 * 4)   // 81920

__device__ __forceinline__ void gemm128_bf16x3(
    const unsigned* __restrict__ Ahi, const unsigned* __restrict__ Alo, int arow0,
    const unsigned* __restrict__ Bhi, const unsigned* __restrict__ Blo, int bcol0,
    float* __restrict__ C, int ldc, bool roundC)
{
    extern __shared__ unsigned smu[];
    const unsigned smBase = (unsigned)__cvta_generic_to_shared(smu);

    const int tid = threadIdx.x;
    const int w = tid >> 5, lane = tid & 31;
    const int g = lane >> 2, t = lane & 3;
    const int rb = (w >> 2) * 64;   // warp row base (2 warps in M)
    const int cb = (w & 3) * 32;    // warp col base (4 warps in N)

    float acc[4][4][4];
#pragma unroll
    for (int mt = 0; mt < 4; ++mt)
#pragma unroll
        for (int nt = 0; nt < 4; ++nt)
#pragma unroll
            for (int r = 0; r < 4; ++r) acc[mt][nt][r] = 0.f;

    const unsigned* srcs[4] = { Ahi, Alo, Bhi, Blo };
    const int base0[4] = { arow0, arow0, bcol0, bcol0 };
    const int dstb[4] = { SA_H, SA_L, SB_H, SB_L };

    auto issue = [&](int k0, int st) {
        const int k2_0 = k0 >> 1;
#pragma unroll
        for (int i = 0; i < 8; ++i) {
            const int idx = tid + i * 256;            // 0..2047
            const int sub = idx >> 9;                 // array 0..3
            const int j = idx & 511;
            const int r = j >> 2, c4 = (j & 3) << 2;  // 16 u32 per row
            cp16(smBase + (unsigned)((dstb[sub] + st * STG_U32 + r * PSTRIDE + c4) << 2),
                 srcs[sub] + (size_t)(base0[sub] + r) * 512 + k2_0 + c4);
        }
        asm volatile("cp.async.commit_group;\n");
    };

    issue(0, 0);
    int st = 0;
    for (int k0 = 0; k0 < 1024; k0 += 32) {
        asm volatile("cp.async.wait_group 0;\n");
        __syncthreads();
        if (k0 + 32 < 1024) issue(k0 + 32, st ^ 1);
        const unsigned* AH = smu + SA_H + st * STG_U32;
        const unsigned* AL = smu + SA_L + st * STG_U32;
        const unsigned* BH = smu + SB_H + st * STG_U32;
        const unsigned* BL = smu + SB_L + st * STG_U32;
#pragma unroll
        for (int ks = 0; ks < 2; ++ks) {
            const int kk2 = ks * 8;
            unsigned ah[4][4], al[4][4], bh[4][2], bl[4][2];
#pragma unroll
            for (int mt = 0; mt < 4; ++mt) {
                const int ro = (rb + mt * 16 + g) * PSTRIDE + kk2;
                ah[mt][0] = AH[ro + t];
                ah[mt][1] = AH[ro + 8 * PSTRIDE + t];
                ah[mt][2] = AH[ro + t + 4];
                ah[mt][3] = AH[ro + 8 * PSTRIDE + t + 4];
                al[mt][0] = AL[ro + t];
                al[mt][1] = AL[ro + 8 * PSTRIDE + t];
                al[mt][2] = AL[ro + t + 4];
                al[mt][3] = AL[ro + 8 * PSTRIDE + t + 4];
            }
#pragma unroll
            for (int nt = 0; nt < 4; ++nt) {
                const int co = (cb + nt * 8 + g) * PSTRIDE + kk2;
                bh[nt][0] = BH[co + t];
                bh[nt][1] = BH[co + t + 4];
                bl[nt][0] = BL[co + t];
                bl[nt][1] = BL[co + t + 4];
            }
#pragma unroll
            for (int mt = 0; mt < 4; ++mt)
#pragma unroll
                for (int nt = 0; nt < 4; ++nt) {
                    mma_bf16(acc[mt][nt], al[mt], bh[nt]);   // lo*hi
                    mma_bf16(acc[mt][nt], ah[mt], bl[nt]);   // hi*lo
                    mma_bf16(acc[mt][nt], ah[mt], bh[nt]);   // hi*hi
                }
        }
        st ^= 1;
    }

#pragma unroll
    for (int mt = 0; mt < 4; ++mt)
#pragma unroll
        for (int nt = 0; nt < 4; ++nt) {
            const int r0 = rb + mt * 16 + g;
            const int c0 = cb + nt * 8 + 2 * t;
            float v0 = acc[mt][nt][0], v1 = acc[mt][nt][1];
            float v2 = acc[mt][nt][2], v3 = acc[mt][nt][3];
            if (roundC) { v0 = tf32r(v0); v1 = tf32r(v1); v2 = tf32r(v2); v3 = tf32r(v3); }
            *(float2*)(C + (size_t)r0 * ldc + c0)       = make_float2(v0, v1);
            *(float2*)(C + (size_t)(r0 + 8) * ldc + c0) = make_float2(v2, v3);
        }
}

// Kernel 1: fused QKV projection; V output rounded to tf32 (PV exactness)
__global__ void __launch_bounds__(256, 2) k_qkv_tc()
{
    const int n0 = blockIdx.x * 128;
    const int m0 = blockIdx.y * 128;
    if (n0 < 1024)
        gemm128_bf16x3(g_hid_hi, g_hid_lo, m0, g_wq_hi, g_wq_lo, n0,
                       g_q + (size_t)m0 * 1024 + n0, 1024, false);
    else if (n0 < 1536)
        gemm128_bf16x3(g_hid_hi, g_hid_lo, m0, g_wk_hi, g_wk_lo, n0 - 1024,
                       g_k + (size_t)m0 * 512 + (n0 - 1024), 512, false);
    else
        gemm128_bf16x3(g_hid_hi, g_hid_lo, m0, g_wv_hi, g_wv_lo, n0 - 1536,
                       g_v + (size_t)m0 * 512 + (n0 - 1536), 512, true);
}

// Kernel 5: output projection from packed attention output
__global__ void __launch_bounds__(256, 2) k_out_tc(float* __restrict__ out)
{
    const int n0 = blockIdx.x * 128;
    const int m0 = blockIdx.y * 128;
    gemm128_bf16x3(g_at_hi, g_at_lo, m0, g_wo_hi, g_wo_lo, n0,
                   out + (size_t)m0 * 1024 + n0, 1024, false);
}

// ---------------------------------------------------------------------------
// Kernel 2: RoPE on q and k -- writes tf32-RNA-rounded values (QK exactness)
// ---------------------------------------------------------------------------
__global__ void k_rope(const float* __restrict__ cosb, const float* __restrict__ sinb)
{
    const int t = blockIdx.x * blockDim.x + threadIdx.x;
    const int total = CBS * 12 * 64;
    if (t >= total) return;
    const int d = t & 63;
    const int head = (t >> 6) % 12;
    const int row = t / (12 * 64);
    const int s = row & (CS - 1);
    const float c1  = cosb[s * CD + d];
    const float sn1 = sinb[s * CD + d];
    const float c2  = cosb[s * CD + d + 64];
    const float sn2 = sinb[s * CD + d + 64];
    float* p;
    if (head < CH) p = g_q + (size_t)row * (CH * CD) + head * CD;
    else           p = g_k + (size_t)row * (CKV * CD) + (head - CH) * CD;
    const float x1 = p[d], x2 = p[d + 64];
    p[d]      = tf32r(x1 * c1 - x2 * sn1);
    p[d + 64] = tf32r(x2 * c2 + x1 * sn2);
}

// ---------------------------------------------------------------------------
// Kernel 3: dt = v_flat @ Wdt ; dyn = exp(A * softplus(dt)) -> g_biasT [h][b][s]
// ---------------------------------------------------------------------------
__global__ void __launch_bounds__(256) k_biask(
    const float* __restrict__ Wdt, const float* __restrict__ Aw)
{
    __shared__ float sW[512 * 8];
    for (int i = threadIdx.x; i < 512 * 8; i += 256) sW[i] = Wdt[i];
    __syncthreads();
    const int warp = threadIdx.x >> 5;
    const int lane = threadIdx.x & 31;
    const int row = blockIdx.x * 8 + warp;
    const float* vrow = g_v + (size_t)row * 512;
    float acc[8];
#pragma unroll
    for (int h = 0; h < 8; ++h) acc[h] = 0.f;
    for (int j = lane; j < 512; j += 32) {
        const float vv = vrow[j];
#pragma unroll
        for (int h = 0; h < 8; ++h) acc[h] = fmaf(vv, sW[j * 8 + h], acc[h]);
    }
#pragma unroll
    for (int off = 16; off > 0; off >>= 1)
#pragma unroll
        for (int h = 0; h < 8; ++h)
            acc[h] += __shfl_xor_sync(0xffffffffu, acc[h], off);
    if (lane < 8) {
        const float dt = acc[lane];
        const float sp = (dt > 20.f) ? dt : log1pf(expf(dt));
        const int b = row >> 11;
        const int s = row & (CS - 1);
        g_biasT[(size_t)(lane * CB + b) * CS + s] = expf(Aw[lane] * sp);
    }
}

// ===========================================================================
// Kernel 4: causal flash attention, tf32 mma (unchanged; passing @134us)
// ===========================================================================
#define KSTR 132
#define VSTR 136
#define PST 68
#define AT_KS 0
#define AT_VS (2 * 64 * KSTR)
#define AT_PS (AT_VS + 2 * 64 * VSTR)
#define AT_BIAS (AT_PS + 128 * PST)
#define ATTN_TC_FLOATS (AT_BIAS + 2 * 64)
#define ATTN_TC_BYTES (ATTN_TC_FLOATS * 4)

__global__ void __launch_bounds__(256, 1) k_attn_tc()
{
    extern __shared__ float sm[];
    float* Ks = sm + AT_KS;
    float* Vs = sm + AT_VS;
    float* Ps = sm + AT_PS;
    float* bias_s = sm + AT_BIAS;
    const unsigned smBase = (unsigned)__cvta_generic_to_shared(sm);

    const int tid = threadIdx.x;
    const int w = tid >> 5, lane = tid & 31;
    const int g = lane >> 2, t = lane & 3;
    const int bh = blockIdx.x;
    const int b = bh >> 3;
    const int h = bh & 7;
    const int kvh = h >> 1;
    const int qt = (int)gridDim.y - 1 - (int)blockIdx.y;
    const int q0 = qt * 128;
    const int qw = w * 16;
    const int qg0 = q0 + qw + g;
    const int qg1 = qg0 + 8;

    unsigned aq[16][4];
    {
        const float* qp = g_q + (size_t)(b * CS + qg0) * 1024 + h * 128;
#pragma unroll
        for (int kf = 0; kf < 16; ++kf) {
            aq[kf][0] = __float_as_uint(qp[kf * 8 + t]);
            aq[kf][1] = __float_as_uint(qp[8 * 1024 + kf * 8 + t]);
            aq[kf][2] = __float_as_uint(qp[kf * 8 + t + 4]);
            aq[kf][3] = __float_as_uint(qp[8 * 1024 + kf * 8 + t + 4]);
        }
    }

    float O[16][4];
#pragma unroll
    for (int nt = 0; nt < 16; ++nt)
#pragma unroll
        for (int r = 0; r < 4; ++r) O[nt][r] = 0.f;
    float m0 = -1e30f, m1 = -1e30f, l0 = 0.f, l1 = 0.f;

    const int nkt = 2 * qt + 2;

    auto issue = [&](int kt, int st) {
        const int kbase = kt * 64;
#pragma unroll
        for (int i = 0; i < 8; ++i) {
            const int idx = tid + i * 256;
            const int c = idx >> 5, dc = (idx & 31) << 2;
            const size_t grow = (size_t)(b * CS + kbase + c) * 512 + kvh * 128 + dc;
            cp16(smBase + (unsigned)((AT_KS + st * 64 * KSTR + c * KSTR + dc) << 2), g_k + grow);
            cp16(smBase + (unsigned)((AT_VS + st * 64 * VSTR + c * VSTR + dc) << 2), g_v + grow);
        }
        if (tid < 16)
            cp16(smBase + (unsigned)((AT_BIAS + st * 64 + tid * 4) << 2),
                 g_biasT + (size_t)(h * CB + b) * CS + kbase + tid * 4);
        asm volatile("cp.async.commit_group;\n");
    };

    issue(0, 0);
    int st = 0;
    for (int kt = 0; kt < nkt; ++kt) {
        const int kbase = kt * 64;
        asm volatile("cp.async.wait_group 0;\n");
        __syncthreads();
        if (kt + 1 < nkt) issue(kt + 1, st ^ 1);

        const float* KsS = Ks + st * 64 * KSTR;
        const float* VsS = Vs + st * 64 * VSTR;
        const float* biasS = bias_s + st * 64;

        float sacc[8][4];
#pragma unroll
        for (int nt = 0; nt < 8; ++nt)
#pragma unroll
            for (int r = 0; r < 4; ++r) sacc[nt][r] = 0.f;
#pragma unroll
        for (int kf = 0; kf < 16; ++kf) {
#pragma unroll
            for (int nt = 0; nt < 8; ++nt) {
                unsigned bf[2];
                const float* kp = KsS + (nt * 8 + g) * KSTR + kf * 8 + t;
                bf[0] = __float_as_uint(kp[0]);
                bf[1] = __float_as_uint(kp[4]);
                mma_tf32(sacc[nt], aq[kf], bf);
            }
        }

        float mx0 = -1e30f, mx1 = -1e30f;
#pragma unroll
        for (int nt = 0; nt < 8; ++nt) {
            const int kg = kbase + nt * 8 + 2 * t;
            const float b0 = biasS[nt * 8 + 2 * t];
            const float b1 = biasS[nt * 8 + 2 * t + 1];
            sacc[nt][0] = (kg     <= qg0) ? fmaf(sacc[nt][0], CSCALE, b0) : -1e30f;
            sacc[nt][1] = (kg + 1 <= qg0) ? fmaf(sacc[nt][1], CSCALE, b1) : -1e30f;
            sacc[nt][2] = (kg     <= qg1) ? fmaf(sacc[nt][2], CSCALE, b0) : -1e30f;
            sacc[nt][3] = (kg + 1 <= qg1) ? fmaf(sacc[nt][3], CSCALE, b1) : -1e30f;
            mx0 = fmaxf(mx0, fmaxf(sacc[nt][0], sacc[nt][1]));
            mx1 = fmaxf(mx1, fmaxf(sacc[nt][2], sacc[nt][3]));
        }
        mx0 = fmaxf(mx0, __shfl_xor_sync(0xffffffffu, mx0, 1));
        mx0 = fmaxf(mx0, __shfl_xor_sync(0xffffffffu, mx0, 2));
        mx1 = fmaxf(mx1, __shfl_xor_sync(0xffffffffu, mx1, 1));
        mx1 = fmaxf(mx1, __shfl_xor_sync(0xffffffffu, mx1, 2));

        const float mn0 = fmaxf(m0, mx0);
        const float mn1 = fmaxf(m1, mx1);
        const float alpha0 = __expf(m0 - mn0);
        const float alpha1 = __expf(m1 - mn1);
        float sum0 = 0.f, sum1 = 0.f;
#pragma unroll
        for (int nt = 0; nt < 8; ++nt) {
            const float p0 = tf32r(__expf(sacc[nt][0] - mn0));
            const float p1 = tf32r(__expf(sacc[nt][1] - mn0));
            const float p2 = tf32r(__expf(sacc[nt][2] - mn1));
            const float p3 = tf32r(__expf(sacc[nt][3] - mn1));
            sum0 += p0 + p1;
            sum1 += p2 + p3;
            *(float2*)&Ps[(qw + g) * PST + nt * 8 + 2 * t]     = make_float2(p0, p1);
            *(float2*)&Ps[(qw + g + 8) * PST + nt * 8 + 2 * t] = make_float2(p2, p3);
        }
        sum0 += __shfl_xor_sync(0xffffffffu, sum0, 1);
        sum0 += __shfl_xor_sync(0xffffffffu, sum0, 2);
        sum1 += __shfl_xor_sync(0xffffffffu, sum1, 1);
        sum1 += __shfl_xor_sync(0xffffffffu, sum1, 2);
        l0 = l0 * alpha0 + sum0;  m0 = mn0;
        l1 = l1 * alpha1 + sum1;  m1 = mn1;

#pragma unroll
        for (int nt = 0; nt < 16; ++nt) {
            O[nt][0] *= alpha0; O[nt][1] *= alpha0;
            O[nt][2] *= alpha1; O[nt][3] *= alpha1;
        }

        __syncwarp();
#pragma unroll
        for (int kf = 0; kf < 8; ++kf) {
            unsigned ap[4];
            const float* pp = Ps + (qw + g) * PST + kf * 8 + t;
            ap[0] = __float_as_uint(pp[0]);
            ap[1] = __float_as_uint(pp[8 * PST]);
            ap[2] = __float_as_uint(pp[4]);
            ap[3] = __float_as_uint(pp[8 * PST + 4]);
#pragma unroll
            for (int nt = 0; nt < 16; ++nt) {
                unsigned bf[2];
                const float* vp = VsS + (kf * 8 + t) * VSTR + nt * 8 + g;
                bf[0] = __float_as_uint(vp[0]);
                bf[1] = __float_as_uint(vp[4 * VSTR]);
                mma_tf32(O[nt], ap, bf);
            }
        }
        __syncthreads();
        st ^= 1;
    }

    // epilogue: normalize and pack to bf16x3 operand layout for k_out.
    const float inv0 = 1.f / l0;
    const float inv1 = 1.f / l1;
    const size_t r0 = (size_t)(b * CS + qg0) * 512 + h * 64;
    const size_t r1 = (size_t)(b * CS + qg1) * 512 + h * 64;
#pragma unroll
    for (int nt = 0; nt < 16; ++nt) {
        unsigned hi, lo;
        bf16x3_pack(O[nt][0] * inv0, O[nt][1] * inv0, hi, lo);
        g_at_hi[r0 + nt * 4 + t] = hi;
        g_at_lo[r0 + nt * 4 + t] = lo;
        bf16x3_pack(O[nt][2] * inv1, O[nt][3] * inv1, hi, lo);
        g_at_hi[r1 + nt * 4 + t] = hi;
        g_at_lo[r1 + nt * 4 + t] = lo;
    }
}

// ---------------------------------------------------------------------------
extern "C" void kernel_launch(void* const* d_in, const int* in_sizes, int n_in,
                              void* d_out, int out_size)
{
    const float* hidden = (const float*)d_in[0];
    const float* Wq     = (const float*)d_in[1];
    const float* Wk     = (const float*)d_in[2];
    const float* Wv     = (const float*)d_in[3];
    const float* Wdt    = (const float*)d_in[4];
    const float* Aw     = (const float*)d_in[5];
    const float* Wo     = (const float*)d_in[6];
    const float* cosb   = (const float*)d_in[7];
    const float* sinb   = (const float*)d_in[8];
    float* out = (float*)d_out;

    cudaFuncSetAttribute(k_qkv_tc,  cudaFuncAttributeMaxDynamicSharedMemorySize, GEMM_SMEM_BYTES);
    cudaFuncSetAttribute(k_out_tc,  cudaFuncAttributeMaxDynamicSharedMemorySize, GEMM_SMEM_BYTES);
    cudaFuncSetAttribute(k_attn_tc, cudaFuncAttributeMaxDynamicSharedMemorySize, ATTN_TC_BYTES);

    // one-time packs; destinations resolved inside device code
    k_cvtA<<<(CBS * 512 + 255) / 256, 256>>>(hidden);
    k_cvtW<<<dim3(16, 32), 256>>>(Wq, 1, 1024);
    k_cvtW<<<dim3(16, 16), 256>>>(Wk, 2, 512);
    k_cvtW<<<dim3(16, 16), 256>>>(Wv, 3, 512);
    k_cvtW<<<dim3(16, 32), 256>>>(Wo, 4, 1024);

    k_qkv_tc<<<dim3(16, 32), 256, GEMM_SMEM_BYTES>>>();
    k_rope<<<(CBS * 12 * 64 + 255) / 256, 256>>>(cosb, sinb);
    k_biask<<<CBS / 8, 256>>>(Wdt, Aw);
    k_attn_tc<<<dim3(16, 16), 256, ATTN_TC_BYTES>>>();
    k_out_tc<<<dim3(8, 32), 256, GEMM_SMEM_BYTES>>>(out);
}